// round 1
// baseline (speedup 1.0000x reference)
#include <cuda_runtime.h>

#define N_NODES 20000
#define F 256
#define R 32
#define NEI2 (R * R)
#define BN_EPS 1e-5f

// ---------------- scratch (no allocations allowed) ----------------
__device__ float g_K[N_NODES];
__device__ float g_Q[N_NODES];
__device__ float g_agg[(size_t)N_NODES * F];   // aggregated input rows
__device__ float g_fin[(size_t)N_NODES * F];   // pre-BN final_h
__device__ float g_colsum[F];
__device__ float g_colsumsq[F];

__device__ __forceinline__ float neg_inf() { return __int_as_float(0xff800000u); }

// ---------------- kernel 0: zero BN accumulators ----------------
__global__ void zero_kernel() {
    int t = threadIdx.x;
    if (t < F) { g_colsum[t] = 0.0f; g_colsumsq[t] = 0.0f; }
}

// ---------------- kernel 1: Key/Query scalars (one warp per node) ----------------
__global__ void kq_kernel(const float* __restrict__ input,
                          const float* __restrict__ Wk,
                          const float* __restrict__ Wq) {
    int warp = (blockIdx.x * blockDim.x + threadIdx.x) >> 5;
    int lane = threadIdx.x & 31;
    if (warp >= N_NODES) return;
    const float4* row = (const float4*)(input + (size_t)warp * F);
    const float4* wk4 = (const float4*)Wk;
    const float4* wq4 = (const float4*)Wq;
    float sk = 0.0f, sq = 0.0f;
#pragma unroll
    for (int i = 0; i < 2; i++) {
        int idx = i * 32 + lane;          // 64 float4 per row
        float4 x = row[idx];
        float4 a = wk4[idx];
        float4 b = wq4[idx];
        sk += x.x * a.x + x.y * a.y + x.z * a.z + x.w * a.w;
        sq += x.x * b.x + x.y * b.y + x.z * b.z + x.w * b.w;
    }
#pragma unroll
    for (int o = 16; o; o >>= 1) {
        sk += __shfl_xor_sync(0xffffffffu, sk, o);
        sq += __shfl_xor_sync(0xffffffffu, sq, o);
    }
    if (lane == 0) { g_K[warp] = sk; g_Q[warp] = sq; }
}

// ---------------- kernel 2: attention softmax + input aggregation ----------------
// one block (256 threads) per node.
__global__ void agg_kernel(const float* __restrict__ input,
                           const int* __restrict__ rf) {
    __shared__ float w_sm[R];
    __shared__ int   id_sm[R];
    int i = blockIdx.x;
    int t = threadIdx.x;
    if (t < R) {  // warp 0 entirely
        int rid = rf[i * R + t];
        float v = (rid == N_NODES - 1) ? -3.0e38f : g_K[i] * g_Q[rid];
        float m = v;
#pragma unroll
        for (int o = 16; o; o >>= 1) m = fmaxf(m, __shfl_xor_sync(0xffffffffu, m, o));
        float e = expf(v - m);   // masked: exp(-huge) = 0; all-masked: exp(0)=1 -> uniform
        float s = e;
#pragma unroll
        for (int o = 16; o; o >>= 1) s += __shfl_xor_sync(0xffffffffu, s, o);
        w_sm[t] = e / s;
        id_sm[t] = rid;
    }
    __syncthreads();
    float acc = input[(size_t)i * F + t];
#pragma unroll 8
    for (int j = 0; j < R; j++) {
        acc += w_sm[j] * input[(size_t)id_sm[j] * F + t];
    }
    g_agg[(size_t)i * F + t] = acc;
}

// ---------------- kernel 3: GEMM  g_fin = g_agg[20000x256] @ W[256x256] ----------------
#define GBM 128
#define GBN 64
#define GBK 16
__global__ void gemm_kernel(const float* __restrict__ B) {
    __shared__ float As[GBK][GBM];
    __shared__ float Bs[GBK][GBN];
    int bm = blockIdx.x * GBM;
    int bn = blockIdx.y * GBN;
    int t = threadIdx.x;           // 256 threads
    int tx = t & 15, ty = t >> 4;  // 16x16
    float acc[8][4];
#pragma unroll
    for (int r = 0; r < 8; r++)
#pragma unroll
        for (int c = 0; c < 4; c++) acc[r][c] = 0.0f;

    for (int kt = 0; kt < F; kt += GBK) {
        // A tile: rows bm..bm+127, cols kt..kt+15. thread: row=t>>1, 8 contiguous k
        {
            int row = t >> 1;
            int kc = (t & 1) * 8;
            int gr = bm + row;
            float4 v0, v1;
            if (gr < N_NODES) {
                const float* src = g_agg + (size_t)gr * F + kt + kc;
                v0 = *(const float4*)src;
                v1 = *(const float4*)(src + 4);
            } else {
                v0 = make_float4(0, 0, 0, 0);
                v1 = v0;
            }
            As[kc + 0][row] = v0.x; As[kc + 1][row] = v0.y;
            As[kc + 2][row] = v0.z; As[kc + 3][row] = v0.w;
            As[kc + 4][row] = v1.x; As[kc + 5][row] = v1.y;
            As[kc + 6][row] = v1.z; As[kc + 7][row] = v1.w;
        }
        // B tile: k = t>>4, col = (t&15)*4
        {
            int k = t >> 4;
            int c = (t & 15) * 4;
            float4 v = *(const float4*)(B + (size_t)(kt + k) * F + bn + c);
            Bs[k][c + 0] = v.x; Bs[k][c + 1] = v.y;
            Bs[k][c + 2] = v.z; Bs[k][c + 3] = v.w;
        }
        __syncthreads();
#pragma unroll
        for (int kk = 0; kk < GBK; kk++) {
            float a[8], b[4];
#pragma unroll
            for (int r = 0; r < 8; r++) a[r] = As[kk][ty * 8 + r];
#pragma unroll
            for (int c = 0; c < 4; c++) b[c] = Bs[kk][tx * 4 + c];
#pragma unroll
            for (int r = 0; r < 8; r++)
#pragma unroll
                for (int c = 0; c < 4; c++) acc[r][c] += a[r] * b[c];
        }
        __syncthreads();
    }
#pragma unroll
    for (int r = 0; r < 8; r++) {
        int gr = bm + ty * 8 + r;
        if (gr < N_NODES) {
#pragma unroll
            for (int c = 0; c < 4; c++)
                g_fin[(size_t)gr * F + bn + tx * 4 + c] = acc[r][c];
        }
    }
}

// ---------------- kernel 4: per-column sums for BN ----------------
__global__ void colsum_kernel() {
    int c = threadIdx.x;  // 256 threads = one column each
    float s = 0.0f, s2 = 0.0f;
    for (int r = blockIdx.x; r < N_NODES; r += gridDim.x) {
        float x = g_fin[(size_t)r * F + c];
        s += x;
        s2 += x * x;
    }
    atomicAdd(&g_colsum[c], s);
    atomicAdd(&g_colsumsq[c], s2);
}

// ---------------- kernel 5: batchnorm + relu -> out ----------------
__global__ void bn_kernel(const float* __restrict__ gamma,
                          const float* __restrict__ beta,
                          float* __restrict__ out) {
    int idx = blockIdx.x * blockDim.x + threadIdx.x;
    if (idx >= N_NODES * F) return;
    int c = idx & (F - 1);
    const float invn = 1.0f / (float)N_NODES;
    float mean = g_colsum[c] * invn;
    float var = g_colsumsq[c] * invn - mean * mean;
    float x = g_fin[idx];
    float y = gamma[c] * (x - mean) * (1.0f / sqrtf(var + BN_EPS)) + beta[c];
    out[idx] = fmaxf(y, 0.0f);   // THICKNESS != 2 -> relu
}

// ---------------- kernel 6: copy receptive_field (int -> float) ----------------
__global__ void copyrf_kernel(const int* __restrict__ rf, float* __restrict__ out) {
    int idx = blockIdx.x * blockDim.x + threadIdx.x;
    if (idx < N_NODES * R) out[idx] = (float)rf[idx];
}

// ---------------- kernel 7: 2-hop expansion, exact stable top-32 of 1024 ----------------
#define WPB 4   // warps (nodes) per block; smem = WPB*1024*8B = 32KB
__global__ void expand_kernel(const int* __restrict__ rf,
                              const int* __restrict__ adj,
                              float* __restrict__ out_expand) {
    __shared__ float v_sm[WPB][NEI2];
    __shared__ int   id_sm[WPB][NEI2];
    int w = threadIdx.x >> 5;
    int lane = threadIdx.x & 31;
    int i = blockIdx.x * WPB + w;
    if (i >= N_NODES) return;

    float key = g_K[i];
    int rfl = rf[i * R + lane];          // lane holds rf[i][lane]
    float* V = v_sm[w];
    int*   ID = id_sm[w];

    // candidate m = k*32 + lane : neighbor[i][m] = adj[rf[i][m/32]][m%32]
#pragma unroll
    for (int k = 0; k < R; k++) {
        int rk = __shfl_sync(0xffffffffu, rfl, k);
        int id = adj[(size_t)rk * R + lane];
        float v = (id == N_NODES - 1) ? -3.0e38f : key * g_Q[id];
        V[k * 32 + lane] = v;
        ID[k * 32 + lane] = id;
    }
    __syncwarp();

    // per-lane cached local argmax over its column (ties -> smallest k)
    float bestv = neg_inf();
    int bestk = 0;
#pragma unroll
    for (int k = 0; k < R; k++) {
        float x = V[k * 32 + lane];
        if (x > bestv) { bestv = x; bestk = k; }
    }

    // 32 selection rounds: warp argmax, tie-break by smallest global index m
    for (int r = 0; r < R; r++) {
        float v = bestv;
        int m = bestk * 32 + lane;
#pragma unroll
        for (int o = 16; o; o >>= 1) {
            float ov = __shfl_xor_sync(0xffffffffu, v, o);
            int   om = __shfl_xor_sync(0xffffffffu, m, o);
            if (ov > v || (ov == v && om < m)) { v = ov; m = om; }
        }
        int winL = m & 31;
        if (lane == winL) {
            out_expand[(size_t)i * R + r] = (float)ID[m];
            V[m] = neg_inf();
            // rescan only the winning lane's column
            bestv = neg_inf(); bestk = 0;
#pragma unroll
            for (int k = 0; k < R; k++) {
                float x = V[k * 32 + lane];
                if (x > bestv) { bestv = x; bestk = k; }
            }
        }
    }
}

// ---------------- launch ----------------
extern "C" void kernel_launch(void* const* d_in, const int* in_sizes, int n_in,
                              void* d_out, int out_size) {
    const float* input = (const float*)d_in[0];
    const int*   rf    = (const int*)d_in[1];   // [1, N, R]
    const int*   adj   = (const int*)d_in[2];   // [N, R]
    const float* W     = (const float*)d_in[3]; // [1, 256, 256]
    const float* Wk    = (const float*)d_in[4];
    const float* Wq    = (const float*)d_in[5];
    const float* gamma = (const float*)d_in[6];
    const float* beta  = (const float*)d_in[7];
    float* out = (float*)d_out;

    zero_kernel<<<1, 256>>>();
    kq_kernel<<<(N_NODES * 32 + 255) / 256, 256>>>(input, Wk, Wq);
    agg_kernel<<<N_NODES, 256>>>(input, rf);
    dim3 gg((N_NODES + GBM - 1) / GBM, F / GBN);
    gemm_kernel<<<gg, 256>>>(W);
    colsum_kernel<<<256, 256>>>();
    bn_kernel<<<(N_NODES * F + 255) / 256, 256>>>(gamma, beta, out);

    // second output (new_receptive_field) if the harness expects it
    if (out_size >= N_NODES * F + 2 * N_NODES * R) {
        copyrf_kernel<<<(N_NODES * R + 255) / 256, 256>>>(rf, out + N_NODES * F);
        expand_kernel<<<(N_NODES + WPB - 1) / WPB, WPB * 32>>>(
            rf, adj, out + N_NODES * F + N_NODES * R);
    }
}

// round 2
// speedup vs baseline: 1.4124x; 1.4124x over previous
#include <cuda_runtime.h>

#define N_NODES 20000
#define F 256
#define R 32
#define NEI2 (R * R)
#define BN_EPS 1e-5f

// ---------------- scratch (no allocations allowed) ----------------
__device__ float g_K[N_NODES];
__device__ float g_Q[N_NODES];
__device__ float g_QA[(size_t)N_NODES * R];    // Q[adj[c][j]] (NaN if masked)
__device__ float g_agg[(size_t)N_NODES * F];   // aggregated input rows
__device__ float g_fin[(size_t)N_NODES * F];   // pre-BN final_h
__device__ float g_colsum[F];
__device__ float g_colsumsq[F];

__device__ __forceinline__ float neg_inf() { return __int_as_float(0xff800000u); }
__device__ __forceinline__ float nan_f()  { return __int_as_float(0x7fffffffu); }

// ---------------- kernel 0: zero BN accumulators ----------------
__global__ void zero_kernel() {
    int t = threadIdx.x;
    if (t < F) { g_colsum[t] = 0.0f; g_colsumsq[t] = 0.0f; }
}

// ---------------- kernel 1: Key/Query scalars (one warp per node) ----------------
__global__ void kq_kernel(const float* __restrict__ input,
                          const float* __restrict__ Wk,
                          const float* __restrict__ Wq) {
    int warp = (blockIdx.x * blockDim.x + threadIdx.x) >> 5;
    int lane = threadIdx.x & 31;
    if (warp >= N_NODES) return;
    const float4* row = (const float4*)(input + (size_t)warp * F);
    const float4* wk4 = (const float4*)Wk;
    const float4* wq4 = (const float4*)Wq;
    float sk = 0.0f, sq = 0.0f;
#pragma unroll
    for (int i = 0; i < 2; i++) {
        int idx = i * 32 + lane;
        float4 x = row[idx];
        float4 a = wk4[idx];
        float4 b = wq4[idx];
        sk += x.x * a.x + x.y * a.y + x.z * a.z + x.w * a.w;
        sq += x.x * b.x + x.y * b.y + x.z * b.z + x.w * b.w;
    }
#pragma unroll
    for (int o = 16; o; o >>= 1) {
        sk += __shfl_xor_sync(0xffffffffu, sk, o);
        sq += __shfl_xor_sync(0xffffffffu, sq, o);
    }
    if (lane == 0) { g_K[warp] = sk; g_Q[warp] = sq; }
}

// ---------------- kernel 1b: QA table  QA[c][j] = Q[adj[c][j]] (NaN if masked) ----------------
__global__ void qa_kernel(const int* __restrict__ adj) {
    int idx = blockIdx.x * blockDim.x + threadIdx.x;
    if (idx >= N_NODES * R) return;
    int id = adj[idx];
    g_QA[idx] = (id == N_NODES - 1) ? nan_f() : g_Q[id];
}

// ---------------- kernel 2: attention softmax + input aggregation ----------------
// 4 nodes per 256-thread block; each thread handles float4 of columns.
#define ANB 4
__global__ void agg_kernel(const float* __restrict__ input,
                           const int* __restrict__ rf) {
    __shared__ float w_sm[ANB][R];
    __shared__ int   id_sm[ANB][R];
    int t = threadIdx.x;
    int ibase = blockIdx.x * ANB;
    if (t < ANB * 32) {            // warps 0..3: one node per warp
        int node = t >> 5, lane = t & 31;
        int i = ibase + node;
        int rid = rf[i * R + lane];
        float v = (rid == N_NODES - 1) ? -3.0e38f : g_K[i] * g_Q[rid];
        float m = v;
#pragma unroll
        for (int o = 16; o; o >>= 1) m = fmaxf(m, __shfl_xor_sync(0xffffffffu, m, o));
        float e = expf(v - m);
        float s = e;
#pragma unroll
        for (int o = 16; o; o >>= 1) s += __shfl_xor_sync(0xffffffffu, s, o);
        w_sm[node][lane] = e / s;
        id_sm[node][lane] = rid;
    }
    __syncthreads();
    int node = t >> 6;
    int c = (t & 63) * 4;
    int i = ibase + node;
    float4 acc = *(const float4*)(input + (size_t)i * F + c);
#pragma unroll
    for (int j = 0; j < R; j++) {
        float wj = w_sm[node][j];
        int id = id_sm[node][j];
        float4 x = *(const float4*)(input + (size_t)id * F + c);
        acc.x += wj * x.x; acc.y += wj * x.y;
        acc.z += wj * x.z; acc.w += wj * x.w;
    }
    *(float4*)(g_agg + (size_t)i * F + c) = acc;
}

// ---------------- kernel 3: GEMM  g_fin = g_agg[20000x256] @ W[256x256] ----------------
// 128x128 tile, 256 threads, 8x8 microtile in 4 quadrants of 4x4.
#define GBM 128
#define GBN 128
#define GBK 16
#define GPAD 4
__global__ void __launch_bounds__(256, 2) gemm_kernel(const float* __restrict__ B) {
    __shared__ float As[GBK][GBM + GPAD];
    __shared__ float Bs[GBK][GBN + GPAD];
    int bm = blockIdx.x * GBM;
    int bn = blockIdx.y * GBN;
    int t = threadIdx.x;
    int tx = t & 15, ty = t >> 4;
    float acc[8][8];
#pragma unroll
    for (int r = 0; r < 8; r++)
#pragma unroll
        for (int c = 0; c < 8; c++) acc[r][c] = 0.0f;

    int arow = t >> 1, akc = (t & 1) * 8;
    int bk = t >> 4, bc = (t & 15) * 8;

    for (int kt = 0; kt < F; kt += GBK) {
        float4 a0, a1, b0, b1;
        int gr = bm + arow;
        if (gr < N_NODES) {
            const float* src = g_agg + (size_t)gr * F + kt + akc;
            a0 = *(const float4*)src;
            a1 = *(const float4*)(src + 4);
        } else {
            a0 = make_float4(0, 0, 0, 0); a1 = a0;
        }
        {
            const float* src = B + (size_t)(kt + bk) * F + bn + bc;
            b0 = *(const float4*)src;
            b1 = *(const float4*)(src + 4);
        }
        __syncthreads();   // previous tile compute done
        As[akc + 0][arow] = a0.x; As[akc + 1][arow] = a0.y;
        As[akc + 2][arow] = a0.z; As[akc + 3][arow] = a0.w;
        As[akc + 4][arow] = a1.x; As[akc + 5][arow] = a1.y;
        As[akc + 6][arow] = a1.z; As[akc + 7][arow] = a1.w;
        *(float4*)&Bs[bk][bc] = b0;
        *(float4*)&Bs[bk][bc + 4] = b1;
        __syncthreads();
#pragma unroll
        for (int kk = 0; kk < GBK; kk++) {
            float ar[8], br[8];
            *(float4*)&ar[0] = *(const float4*)&As[kk][ty * 4];
            *(float4*)&ar[4] = *(const float4*)&As[kk][64 + ty * 4];
            *(float4*)&br[0] = *(const float4*)&Bs[kk][tx * 4];
            *(float4*)&br[4] = *(const float4*)&Bs[kk][64 + tx * 4];
#pragma unroll
            for (int r = 0; r < 8; r++)
#pragma unroll
                for (int c = 0; c < 8; c++) acc[r][c] += ar[r] * br[c];
        }
    }
#pragma unroll
    for (int qr = 0; qr < 2; qr++)
#pragma unroll
        for (int r = 0; r < 4; r++) {
            int gr = bm + qr * 64 + ty * 4 + r;
            if (gr < N_NODES) {
#pragma unroll
                for (int qc = 0; qc < 2; qc++) {
                    float4 v = make_float4(acc[qr * 4 + r][qc * 4 + 0],
                                           acc[qr * 4 + r][qc * 4 + 1],
                                           acc[qr * 4 + r][qc * 4 + 2],
                                           acc[qr * 4 + r][qc * 4 + 3]);
                    *(float4*)(g_fin + (size_t)gr * F + bn + qc * 64 + tx * 4) = v;
                }
            }
        }
}

// ---------------- kernel 4: per-column sums for BN ----------------
__global__ void colsum_kernel() {
    int c = threadIdx.x;
    float s = 0.0f, s2 = 0.0f;
    for (int r = blockIdx.x; r < N_NODES; r += gridDim.x) {
        float x = g_fin[(size_t)r * F + c];
        s += x;
        s2 += x * x;
    }
    atomicAdd(&g_colsum[c], s);
    atomicAdd(&g_colsumsq[c], s2);
}

// ---------------- kernel 5: batchnorm + relu -> out (float4) ----------------
__global__ void bn_kernel(const float* __restrict__ gamma,
                          const float* __restrict__ beta,
                          float* __restrict__ out) {
    int idx4 = blockIdx.x * blockDim.x + threadIdx.x;
    if (idx4 >= N_NODES * F / 4) return;
    int c = (idx4 * 4) & (F - 1);
    const float invn = 1.0f / (float)N_NODES;
    float4 x = *(const float4*)(g_fin + (size_t)idx4 * 4);
    float4 y;
    {
        float mean = g_colsum[c + 0] * invn;
        float var = g_colsumsq[c + 0] * invn - mean * mean;
        y.x = fmaxf(gamma[c + 0] * (x.x - mean) * rsqrtf(var + BN_EPS) + beta[c + 0], 0.0f);
    }
    {
        float mean = g_colsum[c + 1] * invn;
        float var = g_colsumsq[c + 1] * invn - mean * mean;
        y.y = fmaxf(gamma[c + 1] * (x.y - mean) * rsqrtf(var + BN_EPS) + beta[c + 1], 0.0f);
    }
    {
        float mean = g_colsum[c + 2] * invn;
        float var = g_colsumsq[c + 2] * invn - mean * mean;
        y.z = fmaxf(gamma[c + 2] * (x.z - mean) * rsqrtf(var + BN_EPS) + beta[c + 2], 0.0f);
    }
    {
        float mean = g_colsum[c + 3] * invn;
        float var = g_colsumsq[c + 3] * invn - mean * mean;
        y.w = fmaxf(gamma[c + 3] * (x.w - mean) * rsqrtf(var + BN_EPS) + beta[c + 3], 0.0f);
    }
    *(float4*)(out + (size_t)idx4 * 4) = y;
}

// ---------------- kernel 6: copy receptive_field (int -> float) ----------------
__global__ void copyrf_kernel(const int* __restrict__ rf, float* __restrict__ out) {
    int idx = blockIdx.x * blockDim.x + threadIdx.x;
    if (idx < N_NODES * R) out[idx] = (float)rf[idx];
}

// ---------------- kernel 7: 2-hop expansion, exact stable top-32 of 1024 ----------------
// Candidates come from precomputed QA rows (coalesced). Values in smem for rescans;
// per-lane top-2 cache avoids the 32-LDS rescan for a lane's first win.
// Winner ids reconstructed in a parallel epilogue (no id storage).
#define EWPB 8   // warps (nodes) per 256-thread block; smem 33.75KB
__global__ void expand_kernel(const int* __restrict__ rf,
                              const int* __restrict__ adj,
                              float* __restrict__ out_expand) {
    __shared__ float V[EWPB][NEI2];
    __shared__ int   WINM[EWPB][R];
    int w = threadIdx.x >> 5;
    int lane = threadIdx.x & 31;
    int i = blockIdx.x * EWPB + w;
    if (i >= N_NODES) return;

    float key = g_K[i];
    int rfl = rf[i * R + lane];

    // Gather candidates: column k for this lane is candidate m = k*32 + lane.
    // Maintain per-lane top-2 of its column, ties -> smaller k (strict >).
    float b0v = neg_inf(), b1v = neg_inf();
    int b0k = 0, b1k = 0;
#pragma unroll
    for (int k = 0; k < R; k++) {
        int rk = __shfl_sync(0xffffffffu, rfl, k);
        float q = g_QA[(size_t)rk * R + lane];
        float v = (q != q) ? -3.0e38f : key * q;
        V[w][k * 32 + lane] = v;
        if (v > b0v) { b1v = b0v; b1k = b0k; b0v = v; b0k = k; }
        else if (v > b1v) { b1v = v; b1k = k; }
    }
    __syncwarp();

    int pops = 0;
    for (int r = 0; r < R; r++) {
        float v = b0v;
        int m = b0k * 32 + lane;
#pragma unroll
        for (int o = 16; o; o >>= 1) {
            float ov = __shfl_xor_sync(0xffffffffu, v, o);
            int   om = __shfl_xor_sync(0xffffffffu, m, o);
            if (ov > v || (ov == v && om < m)) { v = ov; m = om; }
        }
        if (lane == (m & 31)) {
            WINM[w][r] = m;
            V[w][m] = neg_inf();       // mark consumed
            pops++;
            if (pops == 1) { b0v = b1v; b0k = b1k; }
            else {
                b0v = neg_inf(); b0k = 0;
#pragma unroll
                for (int k = 0; k < R; k++) {
                    float x = V[w][k * 32 + lane];
                    if (x > b0v) { b0v = x; b0k = k; }
                }
            }
        }
    }
    __syncwarp();

    // Epilogue: lane handles round == lane; reconstruct winner id.
    int m = WINM[w][lane];
    int k = m >> 5, j = m & 31;
    int rk = __shfl_sync(0xffffffffu, rfl, k);
    int id = adj[(size_t)rk * R + j];
    out_expand[(size_t)i * R + lane] = (float)id;
}

// ---------------- launch ----------------
extern "C" void kernel_launch(void* const* d_in, const int* in_sizes, int n_in,
                              void* d_out, int out_size) {
    const float* input = (const float*)d_in[0];
    const int*   rf    = (const int*)d_in[1];   // [1, N, R]
    const int*   adj   = (const int*)d_in[2];   // [N, R]
    const float* W     = (const float*)d_in[3]; // [1, 256, 256]
    const float* Wk    = (const float*)d_in[4];
    const float* Wq    = (const float*)d_in[5];
    const float* gamma = (const float*)d_in[6];
    const float* beta  = (const float*)d_in[7];
    float* out = (float*)d_out;

    zero_kernel<<<1, 256>>>();
    kq_kernel<<<(N_NODES * 32 + 255) / 256, 256>>>(input, Wk, Wq);
    qa_kernel<<<(N_NODES * R + 255) / 256, 256>>>(adj);
    agg_kernel<<<N_NODES / ANB, 256>>>(input, rf);
    dim3 gg((N_NODES + GBM - 1) / GBM, F / GBN);
    gemm_kernel<<<gg, 256>>>(W);
    colsum_kernel<<<256, 256>>>();
    bn_kernel<<<(N_NODES * F / 4 + 255) / 256, 256>>>(gamma, beta, out);

    if (out_size >= N_NODES * F + 2 * N_NODES * R) {
        copyrf_kernel<<<(N_NODES * R + 255) / 256, 256>>>(rf, out + N_NODES * F);
        expand_kernel<<<(N_NODES + EWPB - 1) / EWPB, EWPB * 32>>>(
            rf, adj, out + N_NODES * F + N_NODES * R);
    }
}

// round 3
// speedup vs baseline: 1.4774x; 1.0460x over previous
#include <cuda_runtime.h>
#include <cuda_fp16.h>

#define N_NODES 20000
#define F 256
#define R 32
#define NEI2 (R * R)
#define BN_EPS 1e-5f

// ---------------- scratch (no allocations allowed) ----------------
__device__ float g_K[N_NODES];
__device__ float g_Q[N_NODES];
__device__ float g_QA[(size_t)N_NODES * R];    // Q[adj[c][j]] (NaN if masked)
__device__ __align__(16) unsigned short g_inh[(size_t)N_NODES * F];  // fp16 copy of input
__device__ float g_agg[(size_t)N_NODES * F];   // aggregated input rows (fp32)
__device__ float g_fin[(size_t)N_NODES * F];   // pre-BN final_h
__device__ float g_colsum[F];
__device__ float g_colsumsq[F];

__device__ __forceinline__ float neg_inf() { return __int_as_float(0xff800000u); }
__device__ __forceinline__ float nan_f()  { return __int_as_float(0x7fffffffu); }

// ---------------- kernel 1: Key/Query scalars + fp16 copy + BN-acc zeroing ----------------
// one warp per node; block 0 also zeroes the BN accumulators.
__global__ void kq_kernel(const float* __restrict__ input,
                          const float* __restrict__ Wk,
                          const float* __restrict__ Wq) {
    if (blockIdx.x == 0) {
        int t = threadIdx.x;
        if (t < F) { g_colsum[t] = 0.0f; g_colsumsq[t] = 0.0f; }
    }
    int warp = (blockIdx.x * blockDim.x + threadIdx.x) >> 5;
    int lane = threadIdx.x & 31;
    if (warp >= N_NODES) return;
    const float4* row = (const float4*)(input + (size_t)warp * F);
    const float4* wk4 = (const float4*)Wk;
    const float4* wq4 = (const float4*)Wq;
    // lane covers cols [4*lane..4*lane+3] and [128+4*lane..128+4*lane+3]
    float4 x0 = row[lane];
    float4 x1 = row[32 + lane];
    float sk, sq;
    {
        float4 a = wk4[lane], a1 = wk4[32 + lane];
        sk = x0.x * a.x + x0.y * a.y + x0.z * a.z + x0.w * a.w
           + x1.x * a1.x + x1.y * a1.y + x1.z * a1.z + x1.w * a1.w;
        float4 b = wq4[lane], b1 = wq4[32 + lane];
        sq = x0.x * b.x + x0.y * b.y + x0.z * b.z + x0.w * b.w
           + x1.x * b1.x + x1.y * b1.y + x1.z * b1.z + x1.w * b1.w;
    }
    // fp16 copy (two 8B stores, coalesced per half-warp)
    {
        __half2 h0 = __float22half2_rn(make_float2(x0.x, x0.y));
        __half2 h1 = __float22half2_rn(make_float2(x0.z, x0.w));
        __half2 h2 = __float22half2_rn(make_float2(x1.x, x1.y));
        __half2 h3 = __float22half2_rn(make_float2(x1.z, x1.w));
        uint2 p0 = make_uint2(*(unsigned*)&h0, *(unsigned*)&h1);
        uint2 p1 = make_uint2(*(unsigned*)&h2, *(unsigned*)&h3);
        *(uint2*)(g_inh + (size_t)warp * F + 4 * lane)       = p0;
        *(uint2*)(g_inh + (size_t)warp * F + 128 + 4 * lane) = p1;
    }
#pragma unroll
    for (int o = 16; o; o >>= 1) {
        sk += __shfl_xor_sync(0xffffffffu, sk, o);
        sq += __shfl_xor_sync(0xffffffffu, sq, o);
    }
    if (lane == 0) { g_K[warp] = sk; g_Q[warp] = sq; }
}

// ---------------- kernel 1b: QA table  QA[c][j] = Q[adj[c][j]] (NaN if masked) ----------------
__global__ void qa_kernel(const int* __restrict__ adj) {
    int idx = blockIdx.x * blockDim.x + threadIdx.x;
    if (idx >= N_NODES * R) return;
    int id = adj[idx];
    g_QA[idx] = (id == N_NODES - 1) ? nan_f() : g_Q[id];
}

// ---------------- kernel 2: attention softmax + fp16 input aggregation ----------------
// one warp per node; neighbor row = one coalesced 512B warp access; no smem.
__global__ void agg_kernel(const float* __restrict__ input,
                           const int* __restrict__ rf) {
    int gw = (blockIdx.x * blockDim.x + threadIdx.x) >> 5;
    int lane = threadIdx.x & 31;
    if (gw >= N_NODES) return;

    int rid = rf[gw * R + lane];
    float v = (rid == N_NODES - 1) ? -3.0e38f : g_K[gw] * g_Q[rid];
    float m = v;
#pragma unroll
    for (int o = 16; o; o >>= 1) m = fmaxf(m, __shfl_xor_sync(0xffffffffu, m, o));
    float e = expf(v - m);
    float s = e;
#pragma unroll
    for (int o = 16; o; o >>= 1) s += __shfl_xor_sync(0xffffffffu, s, o);
    float wgt = e / s;

    // own row (fp32): lane covers cols 8*lane..8*lane+7
    const float4* own = (const float4*)(input + (size_t)gw * F);
    float4 o0 = own[lane * 2];
    float4 o1 = own[lane * 2 + 1];
    float acc[8] = {o0.x, o0.y, o0.z, o0.w, o1.x, o1.y, o1.z, o1.w};

#pragma unroll 4
    for (int j = 0; j < R; j++) {
        float wj = __shfl_sync(0xffffffffu, wgt, j);
        int id = __shfl_sync(0xffffffffu, rid, j);
        if (wj != 0.0f) {
            uint4 h = *(const uint4*)(g_inh + (size_t)id * F + lane * 8);
            float2 f;
            f = __half22float2(*(__half2*)&h.x); acc[0] += wj * f.x; acc[1] += wj * f.y;
            f = __half22float2(*(__half2*)&h.y); acc[2] += wj * f.x; acc[3] += wj * f.y;
            f = __half22float2(*(__half2*)&h.z); acc[4] += wj * f.x; acc[5] += wj * f.y;
            f = __half22float2(*(__half2*)&h.w); acc[6] += wj * f.x; acc[7] += wj * f.y;
        }
    }
    float4* dst = (float4*)(g_agg + (size_t)gw * F);
    dst[lane * 2]     = make_float4(acc[0], acc[1], acc[2], acc[3]);
    dst[lane * 2 + 1] = make_float4(acc[4], acc[5], acc[6], acc[7]);
}

// ---------------- kernel 3: GEMM  g_fin = g_agg[20000x256] @ W[256x256] ----------------
// 128x128 tile, GBK=32, 256 threads, 8x8 microtile in 4 quadrants of 4x4.
#define GBM 128
#define GBN 128
#define GBK 32
#define GPAD 4
__global__ void __launch_bounds__(256, 2) gemm_kernel(const float* __restrict__ B) {
    __shared__ float As[GBK][GBM + GPAD];
    __shared__ float Bs[GBK][GBN + GPAD];
    int bm = blockIdx.x * GBM;
    int bn = blockIdx.y * GBN;
    int t = threadIdx.x;
    int tx = t & 15, ty = t >> 4;
    float acc[8][8];
#pragma unroll
    for (int r = 0; r < 8; r++)
#pragma unroll
        for (int c = 0; c < 8; c++) acc[r][c] = 0.0f;

    int arow = t >> 1, akc = (t & 1) * 16;   // 128 rows x 32 k; 16 k per thread
    int bk = t >> 3, bc = (t & 7) * 16;      // 32 k x 128 n; 16 n per thread

    for (int kt = 0; kt < F; kt += GBK) {
        float4 a[4], b[4];
        int gr = bm + arow;
        if (gr < N_NODES) {
            const float* src = g_agg + (size_t)gr * F + kt + akc;
#pragma unroll
            for (int q = 0; q < 4; q++) a[q] = *(const float4*)(src + 4 * q);
        } else {
#pragma unroll
            for (int q = 0; q < 4; q++) a[q] = make_float4(0, 0, 0, 0);
        }
        {
            const float* src = B + (size_t)(kt + bk) * F + bn + bc;
#pragma unroll
            for (int q = 0; q < 4; q++) b[q] = *(const float4*)(src + 4 * q);
        }
        __syncthreads();   // previous tile compute done
#pragma unroll
        for (int q = 0; q < 4; q++) {
            As[akc + 4 * q + 0][arow] = a[q].x;
            As[akc + 4 * q + 1][arow] = a[q].y;
            As[akc + 4 * q + 2][arow] = a[q].z;
            As[akc + 4 * q + 3][arow] = a[q].w;
            *(float4*)&Bs[bk][bc + 4 * q] = b[q];
        }
        __syncthreads();
#pragma unroll
        for (int kk = 0; kk < GBK; kk++) {
            float ar[8], br[8];
            *(float4*)&ar[0] = *(const float4*)&As[kk][ty * 4];
            *(float4*)&ar[4] = *(const float4*)&As[kk][64 + ty * 4];
            *(float4*)&br[0] = *(const float4*)&Bs[kk][tx * 4];
            *(float4*)&br[4] = *(const float4*)&Bs[kk][64 + tx * 4];
#pragma unroll
            for (int r = 0; r < 8; r++)
#pragma unroll
                for (int c = 0; c < 8; c++) acc[r][c] += ar[r] * br[c];
        }
    }
#pragma unroll
    for (int qr = 0; qr < 2; qr++)
#pragma unroll
        for (int r = 0; r < 4; r++) {
            int gr = bm + qr * 64 + ty * 4 + r;
            if (gr < N_NODES) {
#pragma unroll
                for (int qc = 0; qc < 2; qc++) {
                    float4 v = make_float4(acc[qr * 4 + r][qc * 4 + 0],
                                           acc[qr * 4 + r][qc * 4 + 1],
                                           acc[qr * 4 + r][qc * 4 + 2],
                                           acc[qr * 4 + r][qc * 4 + 3]);
                    *(float4*)(g_fin + (size_t)gr * F + bn + qc * 64 + tx * 4) = v;
                }
            }
        }
}

// ---------------- kernel 4: per-column sums for BN ----------------
__global__ void colsum_kernel() {
    int c = threadIdx.x;
    float s = 0.0f, s2 = 0.0f;
    for (int r = blockIdx.x; r < N_NODES; r += gridDim.x) {
        float x = g_fin[(size_t)r * F + c];
        s += x;
        s2 += x * x;
    }
    atomicAdd(&g_colsum[c], s);
    atomicAdd(&g_colsumsq[c], s2);
}

// ---------------- kernel 5: batchnorm + relu -> out (float4) ----------------
__global__ void bn_kernel(const float* __restrict__ gamma,
                          const float* __restrict__ beta,
                          float* __restrict__ out) {
    int idx4 = blockIdx.x * blockDim.x + threadIdx.x;
    if (idx4 >= N_NODES * F / 4) return;
    int c = (idx4 * 4) & (F - 1);
    const float invn = 1.0f / (float)N_NODES;
    float4 x = *(const float4*)(g_fin + (size_t)idx4 * 4);
    float4 y;
    {
        float mean = g_colsum[c + 0] * invn;
        float var = g_colsumsq[c + 0] * invn - mean * mean;
        y.x = fmaxf(gamma[c + 0] * (x.x - mean) * rsqrtf(var + BN_EPS) + beta[c + 0], 0.0f);
    }
    {
        float mean = g_colsum[c + 1] * invn;
        float var = g_colsumsq[c + 1] * invn - mean * mean;
        y.y = fmaxf(gamma[c + 1] * (x.y - mean) * rsqrtf(var + BN_EPS) + beta[c + 1], 0.0f);
    }
    {
        float mean = g_colsum[c + 2] * invn;
        float var = g_colsumsq[c + 2] * invn - mean * mean;
        y.z = fmaxf(gamma[c + 2] * (x.z - mean) * rsqrtf(var + BN_EPS) + beta[c + 2], 0.0f);
    }
    {
        float mean = g_colsum[c + 3] * invn;
        float var = g_colsumsq[c + 3] * invn - mean * mean;
        y.w = fmaxf(gamma[c + 3] * (x.w - mean) * rsqrtf(var + BN_EPS) + beta[c + 3], 0.0f);
    }
    *(float4*)(out + (size_t)idx4 * 4) = y;
}

// ---------------- kernel 6: copy receptive_field (int -> float) ----------------
__global__ void copyrf_kernel(const int* __restrict__ rf, float* __restrict__ out) {
    int idx = blockIdx.x * blockDim.x + threadIdx.x;
    if (idx < N_NODES * R) out[idx] = (float)rf[idx];
}

// ---------------- kernel 7: 2-hop expansion, exact stable top-32 of 1024 ----------------
#define EWPB 8   // warps (nodes) per 256-thread block
__global__ void expand_kernel(const int* __restrict__ rf,
                              const int* __restrict__ adj,
                              float* __restrict__ out_expand) {
    __shared__ float V[EWPB][NEI2];
    __shared__ int   WINM[EWPB][R];
    int w = threadIdx.x >> 5;
    int lane = threadIdx.x & 31;
    int i = blockIdx.x * EWPB + w;
    if (i >= N_NODES) return;

    float key = g_K[i];
    int rfl = rf[i * R + lane];

    // column k for this lane is candidate m = k*32 + lane; keep per-lane top-2
    float b0v = neg_inf(), b1v = neg_inf();
    int b0k = 0, b1k = 0;
#pragma unroll
    for (int k = 0; k < R; k++) {
        int rk = __shfl_sync(0xffffffffu, rfl, k);
        float q = g_QA[(size_t)rk * R + lane];
        float v = (q != q) ? -3.0e38f : key * q;
        V[w][k * 32 + lane] = v;
        if (v > b0v) { b1v = b0v; b1k = b0k; b0v = v; b0k = k; }
        else if (v > b1v) { b1v = v; b1k = k; }
    }
    __syncwarp();

    int pops = 0;
    for (int r = 0; r < R; r++) {
        float v = b0v;
        int m = b0k * 32 + lane;
#pragma unroll
        for (int o = 16; o; o >>= 1) {
            float ov = __shfl_xor_sync(0xffffffffu, v, o);
            int   om = __shfl_xor_sync(0xffffffffu, m, o);
            if (ov > v || (ov == v && om < m)) { v = ov; m = om; }
        }
        if (lane == (m & 31)) {
            WINM[w][r] = m;
            V[w][m] = neg_inf();
            pops++;
            if (pops == 1) { b0v = b1v; b0k = b1k; }
            else {
                b0v = neg_inf(); b0k = 0;
#pragma unroll
                for (int k = 0; k < R; k++) {
                    float x = V[w][k * 32 + lane];
                    if (x > b0v) { b0v = x; b0k = k; }
                }
            }
        }
    }
    __syncwarp();

    // lane handles round == lane; reconstruct winner id
    int m = WINM[w][lane];
    int k = m >> 5, j = m & 31;
    int rk = __shfl_sync(0xffffffffu, rfl, k);
    int id = adj[(size_t)rk * R + j];
    out_expand[(size_t)i * R + lane] = (float)id;
}

// ---------------- launch ----------------
extern "C" void kernel_launch(void* const* d_in, const int* in_sizes, int n_in,
                              void* d_out, int out_size) {
    const float* input = (const float*)d_in[0];
    const int*   rf    = (const int*)d_in[1];   // [1, N, R]
    const int*   adj   = (const int*)d_in[2];   // [N, R]
    const float* W     = (const float*)d_in[3]; // [1, 256, 256]
    const float* Wk    = (const float*)d_in[4];
    const float* Wq    = (const float*)d_in[5];
    const float* gamma = (const float*)d_in[6];
    const float* beta  = (const float*)d_in[7];
    float* out = (float*)d_out;

    kq_kernel<<<(N_NODES * 32 + 255) / 256, 256>>>(input, Wk, Wq);
    qa_kernel<<<(N_NODES * R + 255) / 256, 256>>>(adj);
    agg_kernel<<<(N_NODES * 32 + 255) / 256, 256>>>(input, rf);
    dim3 gg((N_NODES + GBM - 1) / GBM, F / GBN);
    gemm_kernel<<<gg, 256>>>(W);
    colsum_kernel<<<256, 256>>>();
    bn_kernel<<<(N_NODES * F / 4 + 255) / 256, 256>>>(gamma, beta, out);

    if (out_size >= N_NODES * F + 2 * N_NODES * R) {
        copyrf_kernel<<<(N_NODES * R + 255) / 256, 256>>>(rf, out + N_NODES * F);
        expand_kernel<<<(N_NODES + EWPB - 1) / EWPB, EWPB * 32>>>(
            rf, adj, out + N_NODES * F + N_NODES * R);
    }
}

// round 4
// speedup vs baseline: 1.7650x; 1.1946x over previous
#include <cuda_runtime.h>
#include <cuda_fp16.h>

#define N_NODES 20000
#define F 256
#define R 32
#define NEI2 (R * R)
#define BN_EPS 1e-5f

// ---------------- scratch (no allocations allowed) ----------------
__device__ float g_K[N_NODES];
__device__ float g_Q[N_NODES];
__device__ float g_QA[(size_t)N_NODES * R];    // Q[adj[c][j]] (NaN if masked)
__device__ __align__(16) unsigned short g_inh[(size_t)N_NODES * F];  // fp16 copy of input
__device__ float g_agg[(size_t)N_NODES * F];   // aggregated input rows (fp32)
__device__ float g_fin[(size_t)N_NODES * F];   // pre-BN final_h
__device__ float g_colsum[F];
__device__ float g_colsumsq[F];

__device__ __forceinline__ float neg_inf() { return __int_as_float(0xff800000u); }
__device__ __forceinline__ float nan_f()  { return __int_as_float(0x7fffffffu); }

__device__ __forceinline__ unsigned f2tf32(float x) {
    unsigned r;
    asm("cvt.rna.tf32.f32 %0, %1;" : "=r"(r) : "f"(x));
    return r;
}

// ---------------- kernel 1: Key/Query scalars + fp16 copy + BN-acc zeroing ----------------
__global__ void kq_kernel(const float* __restrict__ input,
                          const float* __restrict__ Wk,
                          const float* __restrict__ Wq) {
    if (blockIdx.x == 0) {
        int t = threadIdx.x;
        if (t < F) { g_colsum[t] = 0.0f; g_colsumsq[t] = 0.0f; }
    }
    int warp = (blockIdx.x * blockDim.x + threadIdx.x) >> 5;
    int lane = threadIdx.x & 31;
    if (warp >= N_NODES) return;
    const float4* row = (const float4*)(input + (size_t)warp * F);
    const float4* wk4 = (const float4*)Wk;
    const float4* wq4 = (const float4*)Wq;
    float4 x0 = row[lane];
    float4 x1 = row[32 + lane];
    float sk, sq;
    {
        float4 a = wk4[lane], a1 = wk4[32 + lane];
        sk = x0.x * a.x + x0.y * a.y + x0.z * a.z + x0.w * a.w
           + x1.x * a1.x + x1.y * a1.y + x1.z * a1.z + x1.w * a1.w;
        float4 b = wq4[lane], b1 = wq4[32 + lane];
        sq = x0.x * b.x + x0.y * b.y + x0.z * b.z + x0.w * b.w
           + x1.x * b1.x + x1.y * b1.y + x1.z * b1.z + x1.w * b1.w;
    }
    {
        __half2 h0 = __float22half2_rn(make_float2(x0.x, x0.y));
        __half2 h1 = __float22half2_rn(make_float2(x0.z, x0.w));
        __half2 h2 = __float22half2_rn(make_float2(x1.x, x1.y));
        __half2 h3 = __float22half2_rn(make_float2(x1.z, x1.w));
        uint2 p0 = make_uint2(*(unsigned*)&h0, *(unsigned*)&h1);
        uint2 p1 = make_uint2(*(unsigned*)&h2, *(unsigned*)&h3);
        *(uint2*)(g_inh + (size_t)warp * F + 4 * lane)       = p0;
        *(uint2*)(g_inh + (size_t)warp * F + 128 + 4 * lane) = p1;
    }
#pragma unroll
    for (int o = 16; o; o >>= 1) {
        sk += __shfl_xor_sync(0xffffffffu, sk, o);
        sq += __shfl_xor_sync(0xffffffffu, sq, o);
    }
    if (lane == 0) { g_K[warp] = sk; g_Q[warp] = sq; }
}

// ---------------- kernel 1b: QA table ----------------
__global__ void qa_kernel(const int* __restrict__ adj) {
    int idx = blockIdx.x * blockDim.x + threadIdx.x;
    if (idx >= N_NODES * R) return;
    int id = adj[idx];
    g_QA[idx] = (id == N_NODES - 1) ? nan_f() : g_Q[id];
}

// ---------------- kernel 2: attention softmax + fp16 input aggregation ----------------
__global__ void agg_kernel(const float* __restrict__ input,
                           const int* __restrict__ rf) {
    int gw = (blockIdx.x * blockDim.x + threadIdx.x) >> 5;
    int lane = threadIdx.x & 31;
    if (gw >= N_NODES) return;

    int rid = rf[gw * R + lane];
    float v = (rid == N_NODES - 1) ? -3.0e38f : g_K[gw] * g_Q[rid];
    float m = v;
#pragma unroll
    for (int o = 16; o; o >>= 1) m = fmaxf(m, __shfl_xor_sync(0xffffffffu, m, o));
    float e = expf(v - m);
    float s = e;
#pragma unroll
    for (int o = 16; o; o >>= 1) s += __shfl_xor_sync(0xffffffffu, s, o);
    float wgt = e / s;

    const float4* own = (const float4*)(input + (size_t)gw * F);
    float4 o0 = own[lane * 2];
    float4 o1 = own[lane * 2 + 1];
    float acc[8] = {o0.x, o0.y, o0.z, o0.w, o1.x, o1.y, o1.z, o1.w};

#pragma unroll 4
    for (int j = 0; j < R; j++) {
        float wj = __shfl_sync(0xffffffffu, wgt, j);
        int id = __shfl_sync(0xffffffffu, rid, j);
        if (wj != 0.0f) {
            uint4 h = *(const uint4*)(g_inh + (size_t)id * F + lane * 8);
            float2 f;
            f = __half22float2(*(__half2*)&h.x); acc[0] += wj * f.x; acc[1] += wj * f.y;
            f = __half22float2(*(__half2*)&h.y); acc[2] += wj * f.x; acc[3] += wj * f.y;
            f = __half22float2(*(__half2*)&h.z); acc[4] += wj * f.x; acc[5] += wj * f.y;
            f = __half22float2(*(__half2*)&h.w); acc[6] += wj * f.x; acc[7] += wj * f.y;
        }
    }
    float4* dst = (float4*)(g_agg + (size_t)gw * F);
    dst[lane * 2]     = make_float4(acc[0], acc[1], acc[2], acc[3]);
    dst[lane * 2 + 1] = make_float4(acc[4], acc[5], acc[6], acc[7]);
}

// ---------------- kernel 3: tf32 tensor-core GEMM  g_fin = g_agg @ W ----------------
// Block 128x128, 8 warps (4x2), warp tile 32x64 = 2x8 m16n8k8 tiles.
// As stride 36 / Bs stride 136: fragment LDS is conflict-free (4g+t / 8t+g cover all banks).
#define GBM 128
#define GBN 128
#define GKC 32
#define ASTR 36
#define BSTR 136
__global__ void __launch_bounds__(256, 2) gemm_kernel(const float* __restrict__ B) {
    __shared__ __align__(16) unsigned As[GBM * ASTR];
    __shared__ __align__(16) unsigned Bs[GKC * BSTR];
    int bm = blockIdx.x * GBM;
    int bn = blockIdx.y * GBN;
    int t = threadIdx.x;
    int lane = t & 31;
    int warp = t >> 5;
    int warp_m = warp >> 1;          // 0..3
    int warp_n = warp & 1;           // 0..1
    int g = lane >> 2, tg = lane & 3;
    int m0 = warp_m * 32, n0 = warp_n * 64;

    float acc[2][8][4];
#pragma unroll
    for (int mt = 0; mt < 2; mt++)
#pragma unroll
        for (int nt = 0; nt < 8; nt++)
#pragma unroll
            for (int c = 0; c < 4; c++) acc[mt][nt][c] = 0.0f;

    int arow = t >> 1, akc = (t & 1) * 16;
    int bk = t >> 3, bc = (t & 7) * 16;

    for (int kt = 0; kt < F; kt += GKC) {
        float4 a[4], b[4];
        int gr = bm + arow;
        if (gr < N_NODES) {
            const float* src = g_agg + (size_t)gr * F + kt + akc;
#pragma unroll
            for (int q = 0; q < 4; q++) a[q] = *(const float4*)(src + 4 * q);
        } else {
#pragma unroll
            for (int q = 0; q < 4; q++) a[q] = make_float4(0, 0, 0, 0);
        }
        {
            const float* src = B + (size_t)(kt + bk) * F + bn + bc;
#pragma unroll
            for (int q = 0; q < 4; q++) b[q] = *(const float4*)(src + 4 * q);
        }
        __syncthreads();
#pragma unroll
        for (int q = 0; q < 4; q++) {
            uint4 av = make_uint4(f2tf32(a[q].x), f2tf32(a[q].y), f2tf32(a[q].z), f2tf32(a[q].w));
            *(uint4*)&As[arow * ASTR + akc + 4 * q] = av;
            uint4 bv = make_uint4(f2tf32(b[q].x), f2tf32(b[q].y), f2tf32(b[q].z), f2tf32(b[q].w));
            *(uint4*)&Bs[bk * BSTR + bc + 4 * q] = bv;
        }
        __syncthreads();
#pragma unroll
        for (int kk = 0; kk < 4; kk++) {
            int k8 = kk * 8;
            unsigned af[2][4];
#pragma unroll
            for (int mt = 0; mt < 2; mt++) {
                int r0 = m0 + mt * 16 + g;
                af[mt][0] = As[r0 * ASTR + k8 + tg];
                af[mt][1] = As[(r0 + 8) * ASTR + k8 + tg];
                af[mt][2] = As[r0 * ASTR + k8 + tg + 4];
                af[mt][3] = As[(r0 + 8) * ASTR + k8 + tg + 4];
            }
            unsigned bf[8][2];
#pragma unroll
            for (int nt = 0; nt < 8; nt++) {
                bf[nt][0] = Bs[(k8 + tg) * BSTR + n0 + nt * 8 + g];
                bf[nt][1] = Bs[(k8 + tg + 4) * BSTR + n0 + nt * 8 + g];
            }
#pragma unroll
            for (int mt = 0; mt < 2; mt++)
#pragma unroll
                for (int nt = 0; nt < 8; nt++) {
                    asm volatile(
                        "mma.sync.aligned.m16n8k8.row.col.f32.tf32.tf32.f32 "
                        "{%0,%1,%2,%3}, {%4,%5,%6,%7}, {%8,%9}, {%0,%1,%2,%3};"
                        : "+f"(acc[mt][nt][0]), "+f"(acc[mt][nt][1]),
                          "+f"(acc[mt][nt][2]), "+f"(acc[mt][nt][3])
                        : "r"(af[mt][0]), "r"(af[mt][1]), "r"(af[mt][2]), "r"(af[mt][3]),
                          "r"(bf[nt][0]), "r"(bf[nt][1]));
                }
        }
    }

#pragma unroll
    for (int mt = 0; mt < 2; mt++) {
        int row0 = bm + m0 + mt * 16 + g;
        int row1 = row0 + 8;
#pragma unroll
        for (int nt = 0; nt < 8; nt++) {
            int col = bn + n0 + nt * 8 + 2 * tg;
            if (row0 < N_NODES)
                *(float2*)(g_fin + (size_t)row0 * F + col) =
                    make_float2(acc[mt][nt][0], acc[mt][nt][1]);
            if (row1 < N_NODES)
                *(float2*)(g_fin + (size_t)row1 * F + col) =
                    make_float2(acc[mt][nt][2], acc[mt][nt][3]);
        }
    }
}

// ---------------- kernel 4: per-column sums for BN ----------------
__global__ void colsum_kernel() {
    int c = threadIdx.x;
    float s = 0.0f, s2 = 0.0f;
    for (int r = blockIdx.x; r < N_NODES; r += gridDim.x) {
        float x = g_fin[(size_t)r * F + c];
        s += x;
        s2 += x * x;
    }
    atomicAdd(&g_colsum[c], s);
    atomicAdd(&g_colsumsq[c], s2);
}

// ---------------- kernel 5: batchnorm + relu -> out (float4) ----------------
__global__ void bn_kernel(const float* __restrict__ gamma,
                          const float* __restrict__ beta,
                          float* __restrict__ out) {
    int idx4 = blockIdx.x * blockDim.x + threadIdx.x;
    if (idx4 >= N_NODES * F / 4) return;
    int c = (idx4 * 4) & (F - 1);
    const float invn = 1.0f / (float)N_NODES;
    float4 x = *(const float4*)(g_fin + (size_t)idx4 * 4);
    float4 y;
    {
        float mean = g_colsum[c + 0] * invn;
        float var = g_colsumsq[c + 0] * invn - mean * mean;
        y.x = fmaxf(gamma[c + 0] * (x.x - mean) * rsqrtf(var + BN_EPS) + beta[c + 0], 0.0f);
    }
    {
        float mean = g_colsum[c + 1] * invn;
        float var = g_colsumsq[c + 1] * invn - mean * mean;
        y.y = fmaxf(gamma[c + 1] * (x.y - mean) * rsqrtf(var + BN_EPS) + beta[c + 1], 0.0f);
    }
    {
        float mean = g_colsum[c + 2] * invn;
        float var = g_colsumsq[c + 2] * invn - mean * mean;
        y.z = fmaxf(gamma[c + 2] * (x.z - mean) * rsqrtf(var + BN_EPS) + beta[c + 2], 0.0f);
    }
    {
        float mean = g_colsum[c + 3] * invn;
        float var = g_colsumsq[c + 3] * invn - mean * mean;
        y.w = fmaxf(gamma[c + 3] * (x.w - mean) * rsqrtf(var + BN_EPS) + beta[c + 3], 0.0f);
    }
    *(float4*)(out + (size_t)idx4 * 4) = y;
}

// ---------------- kernel 6: copy receptive_field (int -> float) ----------------
__global__ void copyrf_kernel(const int* __restrict__ rf, float* __restrict__ out) {
    int idx = blockIdx.x * blockDim.x + threadIdx.x;
    if (idx < N_NODES * R) out[idx] = (float)rf[idx];
}

// ---------------- kernel 7: 2-hop expansion, exact stable top-32 of 1024 ----------------
#define EWPB 8
__global__ void expand_kernel(const int* __restrict__ rf,
                              const int* __restrict__ adj,
                              float* __restrict__ out_expand) {
    __shared__ float V[EWPB][NEI2];
    __shared__ int   WINM[EWPB][R];
    int w = threadIdx.x >> 5;
    int lane = threadIdx.x & 31;
    int i = blockIdx.x * EWPB + w;
    if (i >= N_NODES) return;

    float key = g_K[i];
    int rfl = rf[i * R + lane];

    float b0v = neg_inf(), b1v = neg_inf();
    int b0k = 0, b1k = 0;
#pragma unroll
    for (int k = 0; k < R; k++) {
        int rk = __shfl_sync(0xffffffffu, rfl, k);
        float q = g_QA[(size_t)rk * R + lane];
        float v = (q != q) ? -3.0e38f : key * q;
        V[w][k * 32 + lane] = v;
        if (v > b0v) { b1v = b0v; b1k = b0k; b0v = v; b0k = k; }
        else if (v > b1v) { b1v = v; b1k = k; }
    }
    __syncwarp();

    int pops = 0;
    for (int r = 0; r < R; r++) {
        float v = b0v;
        int m = b0k * 32 + lane;
#pragma unroll
        for (int o = 16; o; o >>= 1) {
            float ov = __shfl_xor_sync(0xffffffffu, v, o);
            int   om = __shfl_xor_sync(0xffffffffu, m, o);
            if (ov > v || (ov == v && om < m)) { v = ov; m = om; }
        }
        if (lane == (m & 31)) {
            WINM[w][r] = m;
            V[w][m] = neg_inf();
            pops++;
            if (pops == 1) { b0v = b1v; b0k = b1k; }
            else {
                b0v = neg_inf(); b0k = 0;
#pragma unroll
                for (int k = 0; k < R; k++) {
                    float x = V[w][k * 32 + lane];
                    if (x > b0v) { b0v = x; b0k = k; }
                }
            }
        }
    }
    __syncwarp();

    int m = WINM[w][lane];
    int k = m >> 5, j = m & 31;
    int rk = __shfl_sync(0xffffffffu, rfl, k);
    int id = adj[(size_t)rk * R + j];
    out_expand[(size_t)i * R + lane] = (float)id;
}

// ---------------- launch ----------------
extern "C" void kernel_launch(void* const* d_in, const int* in_sizes, int n_in,
                              void* d_out, int out_size) {
    const float* input = (const float*)d_in[0];
    const int*   rf    = (const int*)d_in[1];
    const int*   adj   = (const int*)d_in[2];
    const float* W     = (const float*)d_in[3];
    const float* Wk    = (const float*)d_in[4];
    const float* Wq    = (const float*)d_in[5];
    const float* gamma = (const float*)d_in[6];
    const float* beta  = (const float*)d_in[7];
    float* out = (float*)d_out;

    kq_kernel<<<(N_NODES * 32 + 255) / 256, 256>>>(input, Wk, Wq);
    qa_kernel<<<(N_NODES * R + 255) / 256, 256>>>(adj);
    agg_kernel<<<(N_NODES * 32 + 255) / 256, 256>>>(input, rf);
    dim3 gg((N_NODES + GBM - 1) / GBM, F / GBN);
    gemm_kernel<<<gg, 256>>>(W);
    colsum_kernel<<<256, 256>>>();
    bn_kernel<<<(N_NODES * F / 4 + 255) / 256, 256>>>(gamma, beta, out);

    if (out_size >= N_NODES * F + 2 * N_NODES * R) {
        copyrf_kernel<<<(N_NODES * R + 255) / 256, 256>>>(rf, out + N_NODES * F);
        expand_kernel<<<(N_NODES + EWPB - 1) / EWPB, EWPB * 32>>>(
            rf, adj, out + N_NODES * F + N_NODES * R);
    }
}

// round 5
// speedup vs baseline: 1.8139x; 1.0277x over previous
#include <cuda_runtime.h>
#include <cuda_fp16.h>

#define N_NODES 20000
#define F 256
#define R 32
#define NEI2 (R * R)
#define BN_EPS 1e-5f

// ---------------- scratch (no allocations allowed) ----------------
__device__ float g_K[N_NODES];
__device__ float g_Q[N_NODES];
__device__ float g_QA[(size_t)N_NODES * R];    // Q[adj[c][j]] (NaN if masked)
__device__ __align__(16) unsigned short g_inh[(size_t)N_NODES * F];  // fp16 copy of input
__device__ __align__(16) float g_agg[(size_t)N_NODES * F];   // aggregated rows, tf32-rounded
__device__ __align__(16) float g_Wt[F * F];                  // W, tf32-rounded
__device__ float g_fin[(size_t)N_NODES * F];   // pre-BN final_h
__device__ float g_colsum[F];
__device__ float g_colsumsq[F];

__device__ __forceinline__ float neg_inf() { return __int_as_float(0xff800000u); }
__device__ __forceinline__ float nan_f()  { return __int_as_float(0x7fffffffu); }

__device__ __forceinline__ unsigned f2tf32(float x) {
    unsigned r;
    asm("cvt.rna.tf32.f32 %0, %1;" : "=r"(r) : "f"(x));
    return r;
}
__device__ __forceinline__ float tf32r(float x) { return __uint_as_float(f2tf32(x)); }

__device__ __forceinline__ void cp16(unsigned dst, const void* src, int sz) {
    asm volatile("cp.async.cg.shared.global [%0], [%1], 16, %2;"
                 :: "r"(dst), "l"(src), "r"(sz));
}

// ---------------- kernel 1: Key/Query scalars + fp16 copy + BN-acc zeroing ----------------
__global__ void kq_kernel(const float* __restrict__ input,
                          const float* __restrict__ Wk,
                          const float* __restrict__ Wq) {
    if (blockIdx.x == 0) {
        int t = threadIdx.x;
        if (t < F) { g_colsum[t] = 0.0f; g_colsumsq[t] = 0.0f; }
    }
    int warp = (blockIdx.x * blockDim.x + threadIdx.x) >> 5;
    int lane = threadIdx.x & 31;
    if (warp >= N_NODES) return;
    const float4* row = (const float4*)(input + (size_t)warp * F);
    const float4* wk4 = (const float4*)Wk;
    const float4* wq4 = (const float4*)Wq;
    float4 x0 = row[lane];
    float4 x1 = row[32 + lane];
    float sk, sq;
    {
        float4 a = wk4[lane], a1 = wk4[32 + lane];
        sk = x0.x * a.x + x0.y * a.y + x0.z * a.z + x0.w * a.w
           + x1.x * a1.x + x1.y * a1.y + x1.z * a1.z + x1.w * a1.w;
        float4 b = wq4[lane], b1 = wq4[32 + lane];
        sq = x0.x * b.x + x0.y * b.y + x0.z * b.z + x0.w * b.w
           + x1.x * b1.x + x1.y * b1.y + x1.z * b1.z + x1.w * b1.w;
    }
    {
        __half2 h0 = __float22half2_rn(make_float2(x0.x, x0.y));
        __half2 h1 = __float22half2_rn(make_float2(x0.z, x0.w));
        __half2 h2 = __float22half2_rn(make_float2(x1.x, x1.y));
        __half2 h3 = __float22half2_rn(make_float2(x1.z, x1.w));
        uint2 p0 = make_uint2(*(unsigned*)&h0, *(unsigned*)&h1);
        uint2 p1 = make_uint2(*(unsigned*)&h2, *(unsigned*)&h3);
        *(uint2*)(g_inh + (size_t)warp * F + 4 * lane)       = p0;
        *(uint2*)(g_inh + (size_t)warp * F + 128 + 4 * lane) = p1;
    }
#pragma unroll
    for (int o = 16; o; o >>= 1) {
        sk += __shfl_xor_sync(0xffffffffu, sk, o);
        sq += __shfl_xor_sync(0xffffffffu, sq, o);
    }
    if (lane == 0) { g_K[warp] = sk; g_Q[warp] = sq; }
}

// ---------------- kernel 1b: QA table + W tf32 conversion + rf copy ----------------
__global__ void qa_kernel(const int* __restrict__ adj,
                          const float* __restrict__ W,
                          const int* __restrict__ rf,
                          float* __restrict__ out_rf) {
    int idx = blockIdx.x * blockDim.x + threadIdx.x;
    if (idx < F * F) g_Wt[idx] = tf32r(W[idx]);
    if (idx >= N_NODES * R) return;
    int id = adj[idx];
    g_QA[idx] = (id == N_NODES - 1) ? nan_f() : g_Q[id];
    if (out_rf) out_rf[idx] = (float)rf[idx];
}

// ---------------- kernel 2: attention softmax + fp16 aggregation (tf32-rounded out) ----------------
__global__ void agg_kernel(const float* __restrict__ input,
                           const int* __restrict__ rf) {
    int gw = (blockIdx.x * blockDim.x + threadIdx.x) >> 5;
    int lane = threadIdx.x & 31;
    if (gw >= N_NODES) return;

    int rid = rf[gw * R + lane];
    float v = (rid == N_NODES - 1) ? -3.0e38f : g_K[gw] * g_Q[rid];
    float m = v;
#pragma unroll
    for (int o = 16; o; o >>= 1) m = fmaxf(m, __shfl_xor_sync(0xffffffffu, m, o));
    float e = expf(v - m);
    float s = e;
#pragma unroll
    for (int o = 16; o; o >>= 1) s += __shfl_xor_sync(0xffffffffu, s, o);
    float wgt = e / s;

    const float4* own = (const float4*)(input + (size_t)gw * F);
    float4 o0 = own[lane * 2];
    float4 o1 = own[lane * 2 + 1];
    float acc[8] = {o0.x, o0.y, o0.z, o0.w, o1.x, o1.y, o1.z, o1.w};

#pragma unroll 4
    for (int j = 0; j < R; j++) {
        float wj = __shfl_sync(0xffffffffu, wgt, j);
        int id = __shfl_sync(0xffffffffu, rid, j);
        if (wj != 0.0f) {
            uint4 h = *(const uint4*)(g_inh + (size_t)id * F + lane * 8);
            float2 f;
            f = __half22float2(*(__half2*)&h.x); acc[0] += wj * f.x; acc[1] += wj * f.y;
            f = __half22float2(*(__half2*)&h.y); acc[2] += wj * f.x; acc[3] += wj * f.y;
            f = __half22float2(*(__half2*)&h.z); acc[4] += wj * f.x; acc[5] += wj * f.y;
            f = __half22float2(*(__half2*)&h.w); acc[6] += wj * f.x; acc[7] += wj * f.y;
        }
    }
    float4* dst = (float4*)(g_agg + (size_t)gw * F);
    dst[lane * 2]     = make_float4(tf32r(acc[0]), tf32r(acc[1]), tf32r(acc[2]), tf32r(acc[3]));
    dst[lane * 2 + 1] = make_float4(tf32r(acc[4]), tf32r(acc[5]), tf32r(acc[6]), tf32r(acc[7]));
}

// ---------------- kernel 3: tf32 MMA GEMM with 2-stage cp.async pipeline ----------------
// Block 128x128, 8 warps (4x2), warp tile 32x64 = 2x8 m16n8k8.
// Operands are pre-rounded to tf32 in g_agg / g_Wt -> cp.async straight to smem.
#define GBM 128
#define GBN 128
#define GKC 32
#define ASTR 36
#define BSTR 136
#define ASZ (GBM * ASTR)            // 4608 floats
#define BSZ (GKC * BSTR)            // 4352 floats
#define STG (ASZ + BSZ)             // floats per stage
#define GEMM_SMEM (2 * STG * 4)     // 71680 bytes
#define NKT (F / GKC)               // 8

__global__ void __launch_bounds__(256, 2) gemm_kernel() {
    extern __shared__ float sm[];
    unsigned smb = (unsigned)__cvta_generic_to_shared(sm);
    int bm = blockIdx.x * GBM;
    int bn = blockIdx.y * GBN;
    int t = threadIdx.x;
    int lane = t & 31, warp = t >> 5;
    int warp_m = warp >> 1, warp_n = warp & 1;
    int g = lane >> 2, tg = lane & 3;
    int m0 = warp_m * 32, n0 = warp_n * 64;

    int arow = t >> 1, akc = (t & 1) * 16;
    int bk = t >> 3, bc = (t & 7) * 16;
    int gr = bm + arow;
    int asz = (gr < N_NODES) ? 16 : 0;
    const float* asrc = g_agg + (size_t)(gr < N_NODES ? gr : 0) * F + akc;
    const float* bsrc = g_Wt + (size_t)bk * F + bn + bc;

    float acc[2][8][4];
#pragma unroll
    for (int mt = 0; mt < 2; mt++)
#pragma unroll
        for (int nt = 0; nt < 8; nt++)
#pragma unroll
            for (int c = 0; c < 4; c++) acc[mt][nt][c] = 0.0f;

    // stage issue: copy A tile rows [bm..bm+127] k [kt..kt+31], B rows k cols [bn..bn+127]
    auto issue = [&](int stage, int kt) {
        unsigned ab = smb + (stage * STG + arow * ASTR + akc) * 4;
        const float* as = asrc + kt;
#pragma unroll
        for (int q = 0; q < 4; q++) cp16(ab + q * 16, as + q * 4, asz);
        unsigned bb = smb + (stage * STG + ASZ + bk * BSTR + bc) * 4;
        const float* bs = bsrc + (size_t)kt * F;
#pragma unroll
        for (int q = 0; q < 4; q++) cp16(bb + q * 16, bs + q * 4, 16);
        asm volatile("cp.async.commit_group;");
    };

    issue(0, 0);

    for (int s = 0; s < NKT; s++) {
        if (s + 1 < NKT) {
            issue((s + 1) & 1, (s + 1) * GKC);
            asm volatile("cp.async.wait_group 1;");
        } else {
            asm volatile("cp.async.wait_group 0;");
        }
        __syncthreads();

        const unsigned* As = (const unsigned*)(sm + (s & 1) * STG);
        const unsigned* Bs = (const unsigned*)(sm + (s & 1) * STG + ASZ);
#pragma unroll
        for (int kk = 0; kk < 4; kk++) {
            int k8 = kk * 8;
            unsigned af[2][4];
#pragma unroll
            for (int mt = 0; mt < 2; mt++) {
                int r0 = m0 + mt * 16 + g;
                af[mt][0] = As[r0 * ASTR + k8 + tg];
                af[mt][1] = As[(r0 + 8) * ASTR + k8 + tg];
                af[mt][2] = As[r0 * ASTR + k8 + tg + 4];
                af[mt][3] = As[(r0 + 8) * ASTR + k8 + tg + 4];
            }
            unsigned bf[8][2];
#pragma unroll
            for (int nt = 0; nt < 8; nt++) {
                bf[nt][0] = Bs[(k8 + tg) * BSTR + n0 + nt * 8 + g];
                bf[nt][1] = Bs[(k8 + tg + 4) * BSTR + n0 + nt * 8 + g];
            }
#pragma unroll
            for (int mt = 0; mt < 2; mt++)
#pragma unroll
                for (int nt = 0; nt < 8; nt++) {
                    asm volatile(
                        "mma.sync.aligned.m16n8k8.row.col.f32.tf32.tf32.f32 "
                        "{%0,%1,%2,%3}, {%4,%5,%6,%7}, {%8,%9}, {%0,%1,%2,%3};"
                        : "+f"(acc[mt][nt][0]), "+f"(acc[mt][nt][1]),
                          "+f"(acc[mt][nt][2]), "+f"(acc[mt][nt][3])
                        : "r"(af[mt][0]), "r"(af[mt][1]), "r"(af[mt][2]), "r"(af[mt][3]),
                          "r"(bf[nt][0]), "r"(bf[nt][1]));
                }
        }
        __syncthreads();
    }

#pragma unroll
    for (int mt = 0; mt < 2; mt++) {
        int row0 = bm + m0 + mt * 16 + g;
        int row1 = row0 + 8;
#pragma unroll
        for (int nt = 0; nt < 8; nt++) {
            int col = bn + n0 + nt * 8 + 2 * tg;
            if (row0 < N_NODES)
                *(float2*)(g_fin + (size_t)row0 * F + col) =
                    make_float2(acc[mt][nt][0], acc[mt][nt][1]);
            if (row1 < N_NODES)
                *(float2*)(g_fin + (size_t)row1 * F + col) =
                    make_float2(acc[mt][nt][2], acc[mt][nt][3]);
        }
    }
}

// ---------------- kernel 4: per-column sums for BN ----------------
__global__ void colsum_kernel() {
    int c = threadIdx.x;
    float s = 0.0f, s2 = 0.0f;
    for (int r = blockIdx.x; r < N_NODES; r += gridDim.x) {
        float x = g_fin[(size_t)r * F + c];
        s += x;
        s2 += x * x;
    }
    atomicAdd(&g_colsum[c], s);
    atomicAdd(&g_colsumsq[c], s2);
}

// ---------------- kernel 5: batchnorm + relu -> out (float4) ----------------
__global__ void bn_kernel(const float* __restrict__ gamma,
                          const float* __restrict__ beta,
                          float* __restrict__ out) {
    int idx4 = blockIdx.x * blockDim.x + threadIdx.x;
    if (idx4 >= N_NODES * F / 4) return;
    int c = (idx4 * 4) & (F - 1);
    const float invn = 1.0f / (float)N_NODES;
    float4 x = *(const float4*)(g_fin + (size_t)idx4 * 4);
    float4 y;
    {
        float mean = g_colsum[c + 0] * invn;
        float var = g_colsumsq[c + 0] * invn - mean * mean;
        y.x = fmaxf(gamma[c + 0] * (x.x - mean) * rsqrtf(var + BN_EPS) + beta[c + 0], 0.0f);
    }
    {
        float mean = g_colsum[c + 1] * invn;
        float var = g_colsumsq[c + 1] * invn - mean * mean;
        y.y = fmaxf(gamma[c + 1] * (x.y - mean) * rsqrtf(var + BN_EPS) + beta[c + 1], 0.0f);
    }
    {
        float mean = g_colsum[c + 2] * invn;
        float var = g_colsumsq[c + 2] * invn - mean * mean;
        y.z = fmaxf(gamma[c + 2] * (x.z - mean) * rsqrtf(var + BN_EPS) + beta[c + 2], 0.0f);
    }
    {
        float mean = g_colsum[c + 3] * invn;
        float var = g_colsumsq[c + 3] * invn - mean * mean;
        y.w = fmaxf(gamma[c + 3] * (x.w - mean) * rsqrtf(var + BN_EPS) + beta[c + 3], 0.0f);
    }
    *(float4*)(out + (size_t)idx4 * 4) = y;
}

// ---------------- kernel 7: 2-hop expansion, exact stable top-32 of 1024 ----------------
#define EWPB 8
__global__ void expand_kernel(const int* __restrict__ rf,
                              const int* __restrict__ adj,
                              float* __restrict__ out_expand) {
    __shared__ float V[EWPB][NEI2];
    __shared__ int   WINM[EWPB][R];
    int w = threadIdx.x >> 5;
    int lane = threadIdx.x & 31;
    int i = blockIdx.x * EWPB + w;
    if (i >= N_NODES) return;

    float key = g_K[i];
    int rfl = rf[i * R + lane];

    float b0v = neg_inf(), b1v = neg_inf();
    int b0k = 0, b1k = 0;
#pragma unroll
    for (int k = 0; k < R; k++) {
        int rk = __shfl_sync(0xffffffffu, rfl, k);
        float q = g_QA[(size_t)rk * R + lane];
        float v = (q != q) ? -3.0e38f : key * q;
        V[w][k * 32 + lane] = v;
        if (v > b0v) { b1v = b0v; b1k = b0k; b0v = v; b0k = k; }
        else if (v > b1v) { b1v = v; b1k = k; }
    }
    __syncwarp();

    int pops = 0;
    for (int r = 0; r < R; r++) {
        float v = b0v;
        int m = b0k * 32 + lane;
#pragma unroll
        for (int o = 16; o; o >>= 1) {
            float ov = __shfl_xor_sync(0xffffffffu, v, o);
            int   om = __shfl_xor_sync(0xffffffffu, m, o);
            if (ov > v || (ov == v && om < m)) { v = ov; m = om; }
        }
        if (lane == (m & 31)) {
            WINM[w][r] = m;
            V[w][m] = neg_inf();
            pops++;
            if (pops == 1) { b0v = b1v; b0k = b1k; }
            else {
                b0v = neg_inf(); b0k = 0;
#pragma unroll
                for (int k = 0; k < R; k++) {
                    float x = V[w][k * 32 + lane];
                    if (x > b0v) { b0v = x; b0k = k; }
                }
            }
        }
    }
    __syncwarp();

    int m = WINM[w][lane];
    int k = m >> 5, j = m & 31;
    int rk = __shfl_sync(0xffffffffu, rfl, k);
    int id = adj[(size_t)rk * R + j];
    out_expand[(size_t)i * R + lane] = (float)id;
}

// ---------------- launch ----------------
extern "C" void kernel_launch(void* const* d_in, const int* in_sizes, int n_in,
                              void* d_out, int out_size) {
    const float* input = (const float*)d_in[0];
    const int*   rf    = (const int*)d_in[1];
    const int*   adj   = (const int*)d_in[2];
    const float* W     = (const float*)d_in[3];
    const float* Wk    = (const float*)d_in[4];
    const float* Wq    = (const float*)d_in[5];
    const float* gamma = (const float*)d_in[6];
    const float* beta  = (const float*)d_in[7];
    float* out = (float*)d_out;

    static bool attr_done = false;
    if (!attr_done) {
        cudaFuncSetAttribute(gemm_kernel,
                             cudaFuncAttributeMaxDynamicSharedMemorySize, GEMM_SMEM);
        attr_done = true;
    }

    bool full_out = (out_size >= N_NODES * F + 2 * N_NODES * R);
    float* out_rf = full_out ? (out + N_NODES * F) : nullptr;

    kq_kernel<<<(N_NODES * 32 + 255) / 256, 256>>>(input, Wk, Wq);
    qa_kernel<<<(N_NODES * R + 255) / 256, 256>>>(adj, W, rf, out_rf);
    agg_kernel<<<(N_NODES * 32 + 255) / 256, 256>>>(input, rf);
    dim3 gg((N_NODES + GBM - 1) / GBM, F / GBN);
    gemm_kernel<<<gg, 256, GEMM_SMEM>>>();
    colsum_kernel<<<256, 256>>>();
    bn_kernel<<<(N_NODES * F / 4 + 255) / 256, 256>>>(gamma, beta, out);

    if (full_out) {
        expand_kernel<<<(N_NODES + EWPB - 1) / EWPB, EWPB * 32>>>(
            rf, adj, out + N_NODES * F + N_NODES * R);
    }
}

// round 6
// speedup vs baseline: 2.2775x; 1.2556x over previous
#include <cuda_runtime.h>
#include <cuda_fp16.h>

#define N_NODES 20000
#define F 256
#define R 32
#define NEI2 (R * R)
#define BN_EPS 1e-5f

// ---------------- scratch (no allocations allowed) ----------------
__device__ float g_K[N_NODES];
__device__ float g_Q[N_NODES];
__device__ float g_QA[(size_t)N_NODES * R];    // Q[adj[c][j]] (NaN if masked)
__device__ __align__(16) unsigned short g_inh[(size_t)N_NODES * F];  // fp16 copy of input
__device__ __align__(16) float g_agg[(size_t)N_NODES * F];   // aggregated rows, tf32-rounded
__device__ __align__(16) float g_Wt[F * F];                  // W, tf32-rounded
__device__ float g_fin[(size_t)N_NODES * F];   // pre-BN final_h
__device__ float g_colsum[F];
__device__ float g_colsumsq[F];

__device__ __forceinline__ float nan_f()  { return __int_as_float(0x7fffffffu); }

__device__ __forceinline__ unsigned f2tf32(float x) {
    unsigned r;
    asm("cvt.rna.tf32.f32 %0, %1;" : "=r"(r) : "f"(x));
    return r;
}
__device__ __forceinline__ float tf32r(float x) { return __uint_as_float(f2tf32(x)); }

// order-preserving float -> uint map (except -0.0 < +0.0)
__device__ __forceinline__ unsigned fmap(float v) {
    unsigned b = __float_as_uint(v);
    return (b & 0x80000000u) ? ~b : (b | 0x80000000u);
}

__device__ __forceinline__ void cp16(unsigned dst, const void* src, int sz) {
    asm volatile("cp.async.cg.shared.global [%0], [%1], 16, %2;"
                 :: "r"(dst), "l"(src), "r"(sz));
}

// ---------------- kernel 1: Key/Query scalars + fp16 copy + BN-acc zeroing ----------------
__global__ void kq_kernel(const float* __restrict__ input,
                          const float* __restrict__ Wk,
                          const float* __restrict__ Wq) {
    if (blockIdx.x == 0) {
        int t = threadIdx.x;
        if (t < F) { g_colsum[t] = 0.0f; g_colsumsq[t] = 0.0f; }
    }
    int warp = (blockIdx.x * blockDim.x + threadIdx.x) >> 5;
    int lane = threadIdx.x & 31;
    if (warp >= N_NODES) return;
    const float4* row = (const float4*)(input + (size_t)warp * F);
    const float4* wk4 = (const float4*)Wk;
    const float4* wq4 = (const float4*)Wq;
    float4 x0 = row[lane];
    float4 x1 = row[32 + lane];
    float sk, sq;
    {
        float4 a = wk4[lane], a1 = wk4[32 + lane];
        sk = x0.x * a.x + x0.y * a.y + x0.z * a.z + x0.w * a.w
           + x1.x * a1.x + x1.y * a1.y + x1.z * a1.z + x1.w * a1.w;
        float4 b = wq4[lane], b1 = wq4[32 + lane];
        sq = x0.x * b.x + x0.y * b.y + x0.z * b.z + x0.w * b.w
           + x1.x * b1.x + x1.y * b1.y + x1.z * b1.z + x1.w * b1.w;
    }
    {
        __half2 h0 = __float22half2_rn(make_float2(x0.x, x0.y));
        __half2 h1 = __float22half2_rn(make_float2(x0.z, x0.w));
        __half2 h2 = __float22half2_rn(make_float2(x1.x, x1.y));
        __half2 h3 = __float22half2_rn(make_float2(x1.z, x1.w));
        uint2 p0 = make_uint2(*(unsigned*)&h0, *(unsigned*)&h1);
        uint2 p1 = make_uint2(*(unsigned*)&h2, *(unsigned*)&h3);
        *(uint2*)(g_inh + (size_t)warp * F + 4 * lane)       = p0;
        *(uint2*)(g_inh + (size_t)warp * F + 128 + 4 * lane) = p1;
    }
#pragma unroll
    for (int o = 16; o; o >>= 1) {
        sk += __shfl_xor_sync(0xffffffffu, sk, o);
        sq += __shfl_xor_sync(0xffffffffu, sq, o);
    }
    if (lane == 0) { g_K[warp] = sk; g_Q[warp] = sq; }
}

// ---------------- kernel 1b: QA table + W tf32 conversion + rf copy ----------------
__global__ void qa_kernel(const int* __restrict__ adj,
                          const float* __restrict__ W,
                          const int* __restrict__ rf,
                          float* __restrict__ out_rf) {
    int idx = blockIdx.x * blockDim.x + threadIdx.x;
    if (idx < F * F) g_Wt[idx] = tf32r(W[idx]);
    if (idx >= N_NODES * R) return;
    int id = adj[idx];
    g_QA[idx] = (id == N_NODES - 1) ? nan_f() : g_Q[id];
    if (out_rf) out_rf[idx] = (float)rf[idx];
}

// ---------------- kernel 2: attention softmax + fp16 aggregation (tf32-rounded out) ----------------
__global__ void agg_kernel(const float* __restrict__ input,
                           const int* __restrict__ rf) {
    int gw = (blockIdx.x * blockDim.x + threadIdx.x) >> 5;
    int lane = threadIdx.x & 31;
    if (gw >= N_NODES) return;

    int rid = rf[gw * R + lane];
    float v = (rid == N_NODES - 1) ? -3.0e38f : g_K[gw] * g_Q[rid];
    float m = v;
#pragma unroll
    for (int o = 16; o; o >>= 1) m = fmaxf(m, __shfl_xor_sync(0xffffffffu, m, o));
    float e = expf(v - m);
    float s = e;
#pragma unroll
    for (int o = 16; o; o >>= 1) s += __shfl_xor_sync(0xffffffffu, s, o);
    float wgt = e / s;

    const float4* own = (const float4*)(input + (size_t)gw * F);
    float4 o0 = own[lane * 2];
    float4 o1 = own[lane * 2 + 1];
    float acc[8] = {o0.x, o0.y, o0.z, o0.w, o1.x, o1.y, o1.z, o1.w};

#pragma unroll 4
    for (int j = 0; j < R; j++) {
        float wj = __shfl_sync(0xffffffffu, wgt, j);
        int id = __shfl_sync(0xffffffffu, rid, j);
        if (wj != 0.0f) {
            uint4 h = *(const uint4*)(g_inh + (size_t)id * F + lane * 8);
            float2 f;
            f = __half22float2(*(__half2*)&h.x); acc[0] += wj * f.x; acc[1] += wj * f.y;
            f = __half22float2(*(__half2*)&h.y); acc[2] += wj * f.x; acc[3] += wj * f.y;
            f = __half22float2(*(__half2*)&h.z); acc[4] += wj * f.x; acc[5] += wj * f.y;
            f = __half22float2(*(__half2*)&h.w); acc[6] += wj * f.x; acc[7] += wj * f.y;
        }
    }
    float4* dst = (float4*)(g_agg + (size_t)gw * F);
    dst[lane * 2]     = make_float4(tf32r(acc[0]), tf32r(acc[1]), tf32r(acc[2]), tf32r(acc[3]));
    dst[lane * 2 + 1] = make_float4(tf32r(acc[4]), tf32r(acc[5]), tf32r(acc[6]), tf32r(acc[7]));
}

// ---------------- kernel 7: 2-hop expansion, exact stable top-32 of 1024 (redux.sync) ----------------
#define EWPB 8
__global__ void expand_kernel(const int* __restrict__ rf,
                              const int* __restrict__ adj,
                              float* __restrict__ out_expand) {
    __shared__ unsigned V[EWPB][NEI2];
    __shared__ int WINM[EWPB][R];
    int w = threadIdx.x >> 5;
    int lane = threadIdx.x & 31;
    int i = blockIdx.x * EWPB + w;
    if (i >= N_NODES) return;

    float key = g_K[i];
    int rfl = rf[i * R + lane];

    // load candidates as order-mapped uints; per-lane top-2 of its column
    unsigned b0v = 0, b1v = 0;
    int b0k = 0, b1k = 0;
#pragma unroll
    for (int k = 0; k < R; k++) {
        int rk = __shfl_sync(0xffffffffu, rfl, k);
        float q = g_QA[(size_t)rk * R + lane];
        float v = (q != q) ? -3.0e38f : key * q;
        unsigned mk = fmap(v);
        V[w][k * 32 + lane] = mk;
        if (mk > b0v) { b1v = b0v; b1k = b0k; b0v = mk; b0k = k; }
        else if (mk > b1v) { b1v = mk; b1k = k; }
    }
    __syncwarp();

    int pops = 0;
#pragma unroll 4
    for (int r = 0; r < R; r++) {
        unsigned mx = __reduce_max_sync(0xffffffffu, b0v);
        unsigned m = (unsigned)(b0k * 32 + lane);
        unsigned cand = (b0v == mx) ? m : 0xffffffffu;
        unsigned win = __reduce_min_sync(0xffffffffu, cand);
        if (lane == (win & 31)) {
            WINM[w][r] = (int)win;
            V[w][win] = 0;            // consumed sentinel (strictly below any mapped value)
            pops++;
            if (pops == 1) { b0v = b1v; b0k = b1k; }
            else {
                b0v = 0; b0k = 0;
#pragma unroll
                for (int k = 0; k < R; k++) {
                    unsigned x = V[w][k * 32 + lane];
                    if (x > b0v) { b0v = x; b0k = k; }
                }
            }
        }
    }
    __syncwarp();

    // lane handles round == lane; reconstruct winner id
    int m = WINM[w][lane];
    int k = m >> 5, j = m & 31;
    int rk = __shfl_sync(0xffffffffu, rfl, k);
    out_expand[(size_t)i * R + lane] = (float)adj[(size_t)rk * R + j];
}

// ---------------- kernel 3: tf32 MMA GEMM (cp.async 2-stage) + fused column sums ----------------
#define GBM 128
#define GBN 128
#define GKC 32
#define ASTR 36
#define BSTR 136
#define ASZ (GBM * ASTR)
#define BSZ (GKC * BSTR)
#define STG (ASZ + BSZ)
#define GEMM_SMEM (2 * STG * 4)
#define NKT (F / GKC)

__global__ void __launch_bounds__(256, 2) gemm_kernel() {
    extern __shared__ float sm[];
    unsigned smb = (unsigned)__cvta_generic_to_shared(sm);
    int bm = blockIdx.x * GBM;
    int bn = blockIdx.y * GBN;
    int t = threadIdx.x;
    int lane = t & 31, warp = t >> 5;
    int warp_m = warp >> 1, warp_n = warp & 1;
    int g = lane >> 2, tg = lane & 3;
    int m0 = warp_m * 32, n0 = warp_n * 64;

    int arow = t >> 1, akc = (t & 1) * 16;
    int bk = t >> 3, bc = (t & 7) * 16;
    int gr = bm + arow;
    int asz = (gr < N_NODES) ? 16 : 0;
    const float* asrc = g_agg + (size_t)(gr < N_NODES ? gr : 0) * F + akc;
    const float* bsrc = g_Wt + (size_t)bk * F + bn + bc;

    float acc[2][8][4];
#pragma unroll
    for (int mt = 0; mt < 2; mt++)
#pragma unroll
        for (int nt = 0; nt < 8; nt++)
#pragma unroll
            for (int c = 0; c < 4; c++) acc[mt][nt][c] = 0.0f;

    auto issue = [&](int stage, int kt) {
        unsigned ab = smb + (stage * STG + arow * ASTR + akc) * 4;
        const float* as = asrc + kt;
#pragma unroll
        for (int q = 0; q < 4; q++) cp16(ab + q * 16, as + q * 4, asz);
        unsigned bb = smb + (stage * STG + ASZ + bk * BSTR + bc) * 4;
        const float* bs = bsrc + (size_t)kt * F;
#pragma unroll
        for (int q = 0; q < 4; q++) cp16(bb + q * 16, bs + q * 4, 16);
        asm volatile("cp.async.commit_group;");
    };

    issue(0, 0);

    for (int s = 0; s < NKT; s++) {
        if (s + 1 < NKT) {
            issue((s + 1) & 1, (s + 1) * GKC);
            asm volatile("cp.async.wait_group 1;");
        } else {
            asm volatile("cp.async.wait_group 0;");
        }
        __syncthreads();

        const unsigned* As = (const unsigned*)(sm + (s & 1) * STG);
        const unsigned* Bs = (const unsigned*)(sm + (s & 1) * STG + ASZ);
#pragma unroll
        for (int kk = 0; kk < 4; kk++) {
            int k8 = kk * 8;
            unsigned af[2][4];
#pragma unroll
            for (int mt = 0; mt < 2; mt++) {
                int r0 = m0 + mt * 16 + g;
                af[mt][0] = As[r0 * ASTR + k8 + tg];
                af[mt][1] = As[(r0 + 8) * ASTR + k8 + tg];
                af[mt][2] = As[r0 * ASTR + k8 + tg + 4];
                af[mt][3] = As[(r0 + 8) * ASTR + k8 + tg + 4];
            }
            unsigned bf[8][2];
#pragma unroll
            for (int nt = 0; nt < 8; nt++) {
                bf[nt][0] = Bs[(k8 + tg) * BSTR + n0 + nt * 8 + g];
                bf[nt][1] = Bs[(k8 + tg + 4) * BSTR + n0 + nt * 8 + g];
            }
#pragma unroll
            for (int mt = 0; mt < 2; mt++)
#pragma unroll
                for (int nt = 0; nt < 8; nt++) {
                    asm volatile(
                        "mma.sync.aligned.m16n8k8.row.col.f32.tf32.tf32.f32 "
                        "{%0,%1,%2,%3}, {%4,%5,%6,%7}, {%8,%9}, {%0,%1,%2,%3};"
                        : "+f"(acc[mt][nt][0]), "+f"(acc[mt][nt][1]),
                          "+f"(acc[mt][nt][2]), "+f"(acc[mt][nt][3])
                        : "r"(af[mt][0]), "r"(af[mt][1]), "r"(af[mt][2]), "r"(af[mt][3]),
                          "r"(bf[nt][0]), "r"(bf[nt][1]));
                }
        }
        __syncthreads();
    }

    // store C + fused column sum / sum-of-squares (OOB rows are exact zeros)
#pragma unroll
    for (int mt = 0; mt < 2; mt++) {
        int row0 = bm + m0 + mt * 16 + g;
        int row1 = row0 + 8;
#pragma unroll
        for (int nt = 0; nt < 8; nt++) {
            int col = bn + n0 + nt * 8 + 2 * tg;
            if (row0 < N_NODES)
                *(float2*)(g_fin + (size_t)row0 * F + col) =
                    make_float2(acc[mt][nt][0], acc[mt][nt][1]);
            if (row1 < N_NODES)
                *(float2*)(g_fin + (size_t)row1 * F + col) =
                    make_float2(acc[mt][nt][2], acc[mt][nt][3]);
        }
    }
#pragma unroll
    for (int nt = 0; nt < 8; nt++) {
        float s0 = acc[0][nt][0] + acc[0][nt][2] + acc[1][nt][0] + acc[1][nt][2];
        float s1 = acc[0][nt][1] + acc[0][nt][3] + acc[1][nt][1] + acc[1][nt][3];
        float q0 = acc[0][nt][0] * acc[0][nt][0] + acc[0][nt][2] * acc[0][nt][2]
                 + acc[1][nt][0] * acc[1][nt][0] + acc[1][nt][2] * acc[1][nt][2];
        float q1 = acc[0][nt][1] * acc[0][nt][1] + acc[0][nt][3] * acc[0][nt][3]
                 + acc[1][nt][1] * acc[1][nt][1] + acc[1][nt][3] * acc[1][nt][3];
#pragma unroll
        for (int o = 4; o <= 16; o <<= 1) {
            s0 += __shfl_xor_sync(0xffffffffu, s0, o);
            s1 += __shfl_xor_sync(0xffffffffu, s1, o);
            q0 += __shfl_xor_sync(0xffffffffu, q0, o);
            q1 += __shfl_xor_sync(0xffffffffu, q1, o);
        }
        if (lane < 4) {
            int col = bn + n0 + nt * 8 + 2 * tg;
            atomicAdd(&g_colsum[col], s0);
            atomicAdd(&g_colsum[col + 1], s1);
            atomicAdd(&g_colsumsq[col], q0);
            atomicAdd(&g_colsumsq[col + 1], q1);
        }
    }
}

// ---------------- kernel 5: batchnorm + relu -> out (float4) ----------------
__global__ void bn_kernel(const float* __restrict__ gamma,
                          const float* __restrict__ beta,
                          float* __restrict__ out) {
    int idx4 = blockIdx.x * blockDim.x + threadIdx.x;
    if (idx4 >= N_NODES * F / 4) return;
    int c = (idx4 * 4) & (F - 1);
    const float invn = 1.0f / (float)N_NODES;
    float4 x = *(const float4*)(g_fin + (size_t)idx4 * 4);
    float4 y;
    {
        float mean = g_colsum[c + 0] * invn;
        float var = g_colsumsq[c + 0] * invn - mean * mean;
        y.x = fmaxf(gamma[c + 0] * (x.x - mean) * rsqrtf(var + BN_EPS) + beta[c + 0], 0.0f);
    }
    {
        float mean = g_colsum[c + 1] * invn;
        float var = g_colsumsq[c + 1] * invn - mean * mean;
        y.y = fmaxf(gamma[c + 1] * (x.y - mean) * rsqrtf(var + BN_EPS) + beta[c + 1], 0.0f);
    }
    {
        float mean = g_colsum[c + 2] * invn;
        float var = g_colsumsq[c + 2] * invn - mean * mean;
        y.z = fmaxf(gamma[c + 2] * (x.z - mean) * rsqrtf(var + BN_EPS) + beta[c + 2], 0.0f);
    }
    {
        float mean = g_colsum[c + 3] * invn;
        float var = g_colsumsq[c + 3] * invn - mean * mean;
        y.w = fmaxf(gamma[c + 3] * (x.w - mean) * rsqrtf(var + BN_EPS) + beta[c + 3], 0.0f);
    }
    *(float4*)(out + (size_t)idx4 * 4) = y;
}

// ---------------- launch ----------------
extern "C" void kernel_launch(void* const* d_in, const int* in_sizes, int n_in,
                              void* d_out, int out_size) {
    const float* input = (const float*)d_in[0];
    const int*   rf    = (const int*)d_in[1];
    const int*   adj   = (const int*)d_in[2];
    const float* W     = (const float*)d_in[3];
    const float* Wk    = (const float*)d_in[4];
    const float* Wq    = (const float*)d_in[5];
    const float* gamma = (const float*)d_in[6];
    const float* beta  = (const float*)d_in[7];
    float* out = (float*)d_out;

    static bool attr_done = false;
    if (!attr_done) {
        cudaFuncSetAttribute(gemm_kernel,
                             cudaFuncAttributeMaxDynamicSharedMemorySize, GEMM_SMEM);
        attr_done = true;
    }

    bool full_out = (out_size >= N_NODES * F + 2 * N_NODES * R);
    float* out_rf = full_out ? (out + N_NODES * F) : nullptr;

    kq_kernel<<<(N_NODES * 32 + 255) / 256, 256>>>(input, Wk, Wq);      // 0
    qa_kernel<<<(N_NODES * R + 255) / 256, 256>>>(adj, W, rf, out_rf);  // 1
    agg_kernel<<<(N_NODES * 32 + 255) / 256, 256>>>(input, rf);         // 2
    if (full_out) {                                                      // 3 (profiled slot)
        expand_kernel<<<(N_NODES + EWPB - 1) / EWPB, EWPB * 32>>>(
            rf, adj, out + N_NODES * F + N_NODES * R);
    }
    dim3 gg((N_NODES + GBM - 1) / GBM, F / GBN);
    gemm_kernel<<<gg, 256, GEMM_SMEM>>>();                               // 4
    bn_kernel<<<(N_NODES * F / 4 + 255) / 256, 256>>>(gamma, beta, out); // 5
}

// round 7
// speedup vs baseline: 2.7269x; 1.1973x over previous
#include <cuda_runtime.h>
#include <cuda_fp16.h>

#define N_NODES 20000
#define F 256
#define R 32
#define NEI2 (R * R)
#define BN_EPS 1e-5f

// ---------------- scratch (no allocations allowed) ----------------
__device__ float g_K[N_NODES];
__device__ float g_Q[N_NODES];
__device__ __align__(16) float g_QA[(size_t)N_NODES * R];    // Q[adj[c][j]] (NaN if masked)
__device__ __align__(16) unsigned short g_inh[(size_t)N_NODES * F];  // fp16 copy of input
__device__ __align__(16) float g_agg[(size_t)N_NODES * F];   // aggregated rows, tf32-rounded
__device__ __align__(16) float g_Wt[F * F];                  // W, tf32-rounded
__device__ float g_fin[(size_t)N_NODES * F];   // pre-BN final_h
__device__ float g_colsum[F];
__device__ float g_colsumsq[F];

__device__ __forceinline__ float nan_f()  { return __int_as_float(0x7fffffffu); }

__device__ __forceinline__ unsigned f2tf32(float x) {
    unsigned r;
    asm("cvt.rna.tf32.f32 %0, %1;" : "=r"(r) : "f"(x));
    return r;
}
__device__ __forceinline__ float tf32r(float x) { return __uint_as_float(f2tf32(x)); }

// order-preserving float -> uint map (never 0 for finite inputs)
__device__ __forceinline__ unsigned fmap(float v) {
    unsigned b = __float_as_uint(v);
    return (b & 0x80000000u) ? ~b : (b | 0x80000000u);
}

__device__ __forceinline__ void cp16(unsigned dst, const void* src, int sz) {
    asm volatile("cp.async.cg.shared.global [%0], [%1], 16, %2;"
                 :: "r"(dst), "l"(src), "r"(sz));
}

// ---------------- kernel 1: Key/Query scalars + fp16 copy + BN-acc zeroing ----------------
__global__ void kq_kernel(const float* __restrict__ input,
                          const float* __restrict__ Wk,
                          const float* __restrict__ Wq) {
    if (blockIdx.x == 0) {
        int t = threadIdx.x;
        if (t < F) { g_colsum[t] = 0.0f; g_colsumsq[t] = 0.0f; }
    }
    int warp = (blockIdx.x * blockDim.x + threadIdx.x) >> 5;
    int lane = threadIdx.x & 31;
    if (warp >= N_NODES) return;
    const float4* row = (const float4*)(input + (size_t)warp * F);
    const float4* wk4 = (const float4*)Wk;
    const float4* wq4 = (const float4*)Wq;
    float4 x0 = row[lane];
    float4 x1 = row[32 + lane];
    float sk, sq;
    {
        float4 a = wk4[lane], a1 = wk4[32 + lane];
        sk = x0.x * a.x + x0.y * a.y + x0.z * a.z + x0.w * a.w
           + x1.x * a1.x + x1.y * a1.y + x1.z * a1.z + x1.w * a1.w;
        float4 b = wq4[lane], b1 = wq4[32 + lane];
        sq = x0.x * b.x + x0.y * b.y + x0.z * b.z + x0.w * b.w
           + x1.x * b1.x + x1.y * b1.y + x1.z * b1.z + x1.w * b1.w;
    }
    {
        __half2 h0 = __float22half2_rn(make_float2(x0.x, x0.y));
        __half2 h1 = __float22half2_rn(make_float2(x0.z, x0.w));
        __half2 h2 = __float22half2_rn(make_float2(x1.x, x1.y));
        __half2 h3 = __float22half2_rn(make_float2(x1.z, x1.w));
        uint2 p0 = make_uint2(*(unsigned*)&h0, *(unsigned*)&h1);
        uint2 p1 = make_uint2(*(unsigned*)&h2, *(unsigned*)&h3);
        *(uint2*)(g_inh + (size_t)warp * F + 4 * lane)       = p0;
        *(uint2*)(g_inh + (size_t)warp * F + 128 + 4 * lane) = p1;
    }
#pragma unroll
    for (int o = 16; o; o >>= 1) {
        sk += __shfl_xor_sync(0xffffffffu, sk, o);
        sq += __shfl_xor_sync(0xffffffffu, sq, o);
    }
    if (lane == 0) { g_K[warp] = sk; g_Q[warp] = sq; }
}

// ---------------- kernel 1b: QA table + W tf32 conversion + rf copy ----------------
__global__ void qa_kernel(const int* __restrict__ adj,
                          const float* __restrict__ W,
                          const int* __restrict__ rf,
                          float* __restrict__ out_rf) {
    int idx = blockIdx.x * blockDim.x + threadIdx.x;
    if (idx < F * F) g_Wt[idx] = tf32r(W[idx]);
    if (idx >= N_NODES * R) return;
    int id = adj[idx];
    g_QA[idx] = (id == N_NODES - 1) ? nan_f() : g_Q[id];
    if (out_rf) out_rf[idx] = (float)rf[idx];
}

// ---------------- kernel 2: attention softmax + fp16 aggregation (tf32-rounded out) ----------------
__global__ void agg_kernel(const float* __restrict__ input,
                           const int* __restrict__ rf) {
    int gw = (blockIdx.x * blockDim.x + threadIdx.x) >> 5;
    int lane = threadIdx.x & 31;
    if (gw >= N_NODES) return;

    int rid = rf[gw * R + lane];
    float v = (rid == N_NODES - 1) ? -3.0e38f : g_K[gw] * g_Q[rid];
    float m = v;
#pragma unroll
    for (int o = 16; o; o >>= 1) m = fmaxf(m, __shfl_xor_sync(0xffffffffu, m, o));
    float e = expf(v - m);
    float s = e;
#pragma unroll
    for (int o = 16; o; o >>= 1) s += __shfl_xor_sync(0xffffffffu, s, o);
    float wgt = e / s;

    const float4* own = (const float4*)(input + (size_t)gw * F);
    float4 o0 = own[lane * 2];
    float4 o1 = own[lane * 2 + 1];
    float acc[8] = {o0.x, o0.y, o0.z, o0.w, o1.x, o1.y, o1.z, o1.w};

#pragma unroll 4
    for (int j = 0; j < R; j++) {
        float wj = __shfl_sync(0xffffffffu, wgt, j);
        int id = __shfl_sync(0xffffffffu, rid, j);
        if (wj != 0.0f) {
            uint4 h = *(const uint4*)(g_inh + (size_t)id * F + lane * 8);
            float2 f;
            f = __half22float2(*(__half2*)&h.x); acc[0] += wj * f.x; acc[1] += wj * f.y;
            f = __half22float2(*(__half2*)&h.y); acc[2] += wj * f.x; acc[3] += wj * f.y;
            f = __half22float2(*(__half2*)&h.z); acc[4] += wj * f.x; acc[5] += wj * f.y;
            f = __half22float2(*(__half2*)&h.w); acc[6] += wj * f.x; acc[7] += wj * f.y;
        }
    }
    float4* dst = (float4*)(g_agg + (size_t)gw * F);
    dst[lane * 2]     = make_float4(tf32r(acc[0]), tf32r(acc[1]), tf32r(acc[2]), tf32r(acc[3]));
    dst[lane * 2 + 1] = make_float4(tf32r(acc[4]), tf32r(acc[5]), tf32r(acc[6]), tf32r(acc[7]));
}

// ---------------- kernel 7: 2-hop expansion, exact stable top-32 of 1024 ----------------
// Lane L owns candidates m in [32L, 32L+32) = QA row rf[i][L] (one contiguous row).
// Selection: redux argmax over per-lane top-1 caches; refill of the winner's
// column is warp-cooperative (stride-33 smem, conflict-free) -> zero divergence.
#define EWPB 8
#define VSTR 33
__global__ void expand_kernel(const int* __restrict__ rf,
                              const int* __restrict__ adj,
                              float* __restrict__ out_expand) {
    __shared__ unsigned V[EWPB][R * VSTR];
    __shared__ int WINM[EWPB][R];
    int w = threadIdx.x >> 5;
    int lane = threadIdx.x & 31;
    int i = blockIdx.x * EWPB + w;
    if (i >= N_NODES) return;

    float key = g_K[i];
    int rfl = rf[i * R + lane];

    // load own QA row (8 x float4), keep per-lane top-1 (smallest j on ties)
    unsigned b0v = 0;
    int b0j = 0;
    const float4* qrow = (const float4*)(g_QA + (size_t)rfl * R);
    unsigned* Vrow = &V[w][lane * VSTR];
#pragma unroll
    for (int q = 0; q < 8; q++) {
        float4 x = qrow[q];
        float v0 = (x.x != x.x) ? -3.0e38f : key * x.x;
        float v1 = (x.y != x.y) ? -3.0e38f : key * x.y;
        float v2 = (x.z != x.z) ? -3.0e38f : key * x.z;
        float v3 = (x.w != x.w) ? -3.0e38f : key * x.w;
        unsigned m0 = fmap(v0), m1 = fmap(v1), m2 = fmap(v2), m3 = fmap(v3);
        Vrow[4 * q + 0] = m0;
        Vrow[4 * q + 1] = m1;
        Vrow[4 * q + 2] = m2;
        Vrow[4 * q + 3] = m3;
        if (m0 > b0v) { b0v = m0; b0j = 4 * q + 0; }
        if (m1 > b0v) { b0v = m1; b0j = 4 * q + 1; }
        if (m2 > b0v) { b0v = m2; b0j = 4 * q + 2; }
        if (m3 > b0v) { b0v = m3; b0j = 4 * q + 3; }
    }
    __syncwarp();

#pragma unroll 4
    for (int r = 0; r < R; r++) {
        // global argmax with (value desc, m asc) ordering
        unsigned mx = __reduce_max_sync(0xffffffffu, b0v);
        unsigned cand = (b0v == mx) ? (unsigned)(lane * 32 + b0j) : 0xffffffffu;
        unsigned m = __reduce_min_sync(0xffffffffu, cand);
        if (lane == 0) WINM[w][r] = (int)m;

        // cooperative refill of winner column winL
        int winL = m >> 5, jwin = m & 31;
        unsigned x = V[w][winL * VSTR + lane];
        if (lane == jwin) {
            x = 0;
            V[w][winL * VSTR + jwin] = 0;   // mark consumed
        }
        unsigned mx2 = __reduce_max_sync(0xffffffffu, x);
        unsigned jc = (x == mx2) ? (unsigned)lane : 0xffffffffu;
        unsigned j2 = __reduce_min_sync(0xffffffffu, jc);
        if (lane == winL) { b0v = mx2; b0j = (int)j2; }
        __syncwarp();
    }

    // lane handles round == lane; reconstruct winner id
    int m = WINM[w][lane];
    int k = m >> 5, j = m & 31;
    int rk = __shfl_sync(0xffffffffu, rfl, k);
    out_expand[(size_t)i * R + lane] = (float)adj[(size_t)rk * R + j];
}

// ---------------- kernel 3: tf32 MMA GEMM (cp.async 2-stage) + fused column sums ----------------
#define GBM 128
#define GBN 128
#define GKC 32
#define ASTR 36
#define BSTR 136
#define ASZ (GBM * ASTR)
#define BSZ (GKC * BSTR)
#define STG (ASZ + BSZ)
#define GEMM_SMEM (2 * STG * 4)
#define NKT (F / GKC)

__global__ void __launch_bounds__(256, 2) gemm_kernel() {
    extern __shared__ float sm[];
    unsigned smb = (unsigned)__cvta_generic_to_shared(sm);
    int bm = blockIdx.x * GBM;
    int bn = blockIdx.y * GBN;
    int t = threadIdx.x;
    int lane = t & 31, warp = t >> 5;
    int warp_m = warp >> 1, warp_n = warp & 1;
    int g = lane >> 2, tg = lane & 3;
    int m0 = warp_m * 32, n0 = warp_n * 64;

    int arow = t >> 1, akc = (t & 1) * 16;
    int bk = t >> 3, bc = (t & 7) * 16;
    int gr = bm + arow;
    int asz = (gr < N_NODES) ? 16 : 0;
    const float* asrc = g_agg + (size_t)(gr < N_NODES ? gr : 0) * F + akc;
    const float* bsrc = g_Wt + (size_t)bk * F + bn + bc;

    float acc[2][8][4];
#pragma unroll
    for (int mt = 0; mt < 2; mt++)
#pragma unroll
        for (int nt = 0; nt < 8; nt++)
#pragma unroll
            for (int c = 0; c < 4; c++) acc[mt][nt][c] = 0.0f;

    auto issue = [&](int stage, int kt) {
        unsigned ab = smb + (stage * STG + arow * ASTR + akc) * 4;
        const float* as = asrc + kt;
#pragma unroll
        for (int q = 0; q < 4; q++) cp16(ab + q * 16, as + q * 4, asz);
        unsigned bb = smb + (stage * STG + ASZ + bk * BSTR + bc) * 4;
        const float* bs = bsrc + (size_t)kt * F;
#pragma unroll
        for (int q = 0; q < 4; q++) cp16(bb + q * 16, bs + q * 4, 16);
        asm volatile("cp.async.commit_group;");
    };

    issue(0, 0);

    for (int s = 0; s < NKT; s++) {
        if (s + 1 < NKT) {
            issue((s + 1) & 1, (s + 1) * GKC);
            asm volatile("cp.async.wait_group 1;");
        } else {
            asm volatile("cp.async.wait_group 0;");
        }
        __syncthreads();

        const unsigned* As = (const unsigned*)(sm + (s & 1) * STG);
        const unsigned* Bs = (const unsigned*)(sm + (s & 1) * STG + ASZ);
#pragma unroll
        for (int kk = 0; kk < 4; kk++) {
            int k8 = kk * 8;
            unsigned af[2][4];
#pragma unroll
            for (int mt = 0; mt < 2; mt++) {
                int r0 = m0 + mt * 16 + g;
                af[mt][0] = As[r0 * ASTR + k8 + tg];
                af[mt][1] = As[(r0 + 8) * ASTR + k8 + tg];
                af[mt][2] = As[r0 * ASTR + k8 + tg + 4];
                af[mt][3] = As[(r0 + 8) * ASTR + k8 + tg + 4];
            }
            unsigned bf[8][2];
#pragma unroll
            for (int nt = 0; nt < 8; nt++) {
                bf[nt][0] = Bs[(k8 + tg) * BSTR + n0 + nt * 8 + g];
                bf[nt][1] = Bs[(k8 + tg + 4) * BSTR + n0 + nt * 8 + g];
            }
#pragma unroll
            for (int mt = 0; mt < 2; mt++)
#pragma unroll
                for (int nt = 0; nt < 8; nt++) {
                    asm volatile(
                        "mma.sync.aligned.m16n8k8.row.col.f32.tf32.tf32.f32 "
                        "{%0,%1,%2,%3}, {%4,%5,%6,%7}, {%8,%9}, {%0,%1,%2,%3};"
                        : "+f"(acc[mt][nt][0]), "+f"(acc[mt][nt][1]),
                          "+f"(acc[mt][nt][2]), "+f"(acc[mt][nt][3])
                        : "r"(af[mt][0]), "r"(af[mt][1]), "r"(af[mt][2]), "r"(af[mt][3]),
                          "r"(bf[nt][0]), "r"(bf[nt][1]));
                }
        }
        __syncthreads();
    }

    // store C + fused column sum / sum-of-squares (OOB rows are exact zeros)
#pragma unroll
    for (int mt = 0; mt < 2; mt++) {
        int row0 = bm + m0 + mt * 16 + g;
        int row1 = row0 + 8;
#pragma unroll
        for (int nt = 0; nt < 8; nt++) {
            int col = bn + n0 + nt * 8 + 2 * tg;
            if (row0 < N_NODES)
                *(float2*)(g_fin + (size_t)row0 * F + col) =
                    make_float2(acc[mt][nt][0], acc[mt][nt][1]);
            if (row1 < N_NODES)
                *(float2*)(g_fin + (size_t)row1 * F + col) =
                    make_float2(acc[mt][nt][2], acc[mt][nt][3]);
        }
    }
#pragma unroll
    for (int nt = 0; nt < 8; nt++) {
        float s0 = acc[0][nt][0] + acc[0][nt][2] + acc[1][nt][0] + acc[1][nt][2];
        float s1 = acc[0][nt][1] + acc[0][nt][3] + acc[1][nt][1] + acc[1][nt][3];
        float q0 = acc[0][nt][0] * acc[0][nt][0] + acc[0][nt][2] * acc[0][nt][2]
                 + acc[1][nt][0] * acc[1][nt][0] + acc[1][nt][2] * acc[1][nt][2];
        float q1 = acc[0][nt][1] * acc[0][nt][1] + acc[0][nt][3] * acc[0][nt][3]
                 + acc[1][nt][1] * acc[1][nt][1] + acc[1][nt][3] * acc[1][nt][3];
#pragma unroll
        for (int o = 4; o <= 16; o <<= 1) {
            s0 += __shfl_xor_sync(0xffffffffu, s0, o);
            s1 += __shfl_xor_sync(0xffffffffu, s1, o);
            q0 += __shfl_xor_sync(0xffffffffu, q0, o);
            q1 += __shfl_xor_sync(0xffffffffu, q1, o);
        }
        if (lane < 4) {
            int col = bn + n0 + nt * 8 + 2 * tg;
            atomicAdd(&g_colsum[col], s0);
            atomicAdd(&g_colsum[col + 1], s1);
            atomicAdd(&g_colsumsq[col], q0);
            atomicAdd(&g_colsumsq[col + 1], q1);
        }
    }
}

// ---------------- kernel 5: batchnorm + relu -> out (float4) ----------------
__global__ void bn_kernel(const float* __restrict__ gamma,
                          const float* __restrict__ beta,
                          float* __restrict__ out) {
    int idx4 = blockIdx.x * blockDim.x + threadIdx.x;
    if (idx4 >= N_NODES * F / 4) return;
    int c = (idx4 * 4) & (F - 1);
    const float invn = 1.0f / (float)N_NODES;
    float4 x = *(const float4*)(g_fin + (size_t)idx4 * 4);
    float4 y;
    {
        float mean = g_colsum[c + 0] * invn;
        float var = g_colsumsq[c + 0] * invn - mean * mean;
        y.x = fmaxf(gamma[c + 0] * (x.x - mean) * rsqrtf(var + BN_EPS) + beta[c + 0], 0.0f);
    }
    {
        float mean = g_colsum[c + 1] * invn;
        float var = g_colsumsq[c + 1] * invn - mean * mean;
        y.y = fmaxf(gamma[c + 1] * (x.y - mean) * rsqrtf(var + BN_EPS) + beta[c + 1], 0.0f);
    }
    {
        float mean = g_colsum[c + 2] * invn;
        float var = g_colsumsq[c + 2] * invn - mean * mean;
        y.z = fmaxf(gamma[c + 2] * (x.z - mean) * rsqrtf(var + BN_EPS) + beta[c + 2], 0.0f);
    }
    {
        float mean = g_colsum[c + 3] * invn;
        float var = g_colsumsq[c + 3] * invn - mean * mean;
        y.w = fmaxf(gamma[c + 3] * (x.w - mean) * rsqrtf(var + BN_EPS) + beta[c + 3], 0.0f);
    }
    *(float4*)(out + (size_t)idx4 * 4) = y;
}

// ---------------- launch ----------------
extern "C" void kernel_launch(void* const* d_in, const int* in_sizes, int n_in,
                              void* d_out, int out_size) {
    const float* input = (const float*)d_in[0];
    const int*   rf    = (const int*)d_in[1];
    const int*   adj   = (const int*)d_in[2];
    const float* W     = (const float*)d_in[3];
    const float* Wk    = (const float*)d_in[4];
    const float* Wq    = (const float*)d_in[5];
    const float* gamma = (const float*)d_in[6];
    const float* beta  = (const float*)d_in[7];
    float* out = (float*)d_out;

    static bool attr_done = false;
    if (!attr_done) {
        cudaFuncSetAttribute(gemm_kernel,
                             cudaFuncAttributeMaxDynamicSharedMemorySize, GEMM_SMEM);
        attr_done = true;
    }

    bool full_out = (out_size >= N_NODES * F + 2 * N_NODES * R);
    float* out_rf = full_out ? (out + N_NODES * F) : nullptr;

    kq_kernel<<<(N_NODES * 32 + 255) / 256, 256>>>(input, Wk, Wq);      // 0
    qa_kernel<<<(N_NODES * R + 255) / 256, 256>>>(adj, W, rf, out_rf);  // 1
    agg_kernel<<<(N_NODES * 32 + 255) / 256, 256>>>(input, rf);         // 2
    if (full_out) {                                                      // 3 (profiled slot)
        expand_kernel<<<(N_NODES + EWPB - 1) / EWPB, EWPB * 32>>>(
            rf, adj, out + N_NODES * F + N_NODES * R);
    }
    dim3 gg((N_NODES + GBM - 1) / GBM, F / GBN);
    gemm_kernel<<<gg, 256, GEMM_SMEM>>>();                               // 4
    bn_kernel<<<(N_NODES * F / 4 + 255) / 256, 256>>>(gamma, beta, out); // 5
}